// round 12
// baseline (speedup 1.0000x reference)
#include <cuda_runtime.h>
#include <cuda_bf16.h>
#include <math.h>

// Problem constants
#define BATCH 4
#define SEQ   2048
#define DIMC  1024
#define NH    16
#define HD    64
#define HID   2048
#define MTOK  (BATCH * SEQ)   // 8192 tokens

// ===========================================================================
// Scratch (static device globals; allocations forbidden)
// ===========================================================================
__device__ float g_qkv[(size_t)MTOK * 3 * DIMC];   // fp32 qkv (pre-rope)
__device__ float g_x1[(size_t)MTOK * HID];
__device__ float g_x2[(size_t)MTOK * HID];

// Separate hi/lo bf16 planes (non-redundant split scheme)
__device__ __align__(256) __nv_bfloat16 g_xhi[(size_t)MTOK * DIMC];
__device__ __align__(256) __nv_bfloat16 g_xlo[(size_t)MTOK * DIMC];
__device__ __align__(256) __nv_bfloat16 g_ahi[(size_t)MTOK * DIMC];   // attn out
__device__ __align__(256) __nv_bfloat16 g_alo[(size_t)MTOK * DIMC];
__device__ __align__(256) __nv_bfloat16 g_phi[(size_t)MTOK * DIMC];   // proj out
__device__ __align__(256) __nv_bfloat16 g_plo[(size_t)MTOK * DIMC];
__device__ __align__(256) __nv_bfloat16 g_hhi[(size_t)MTOK * HID];    // swiglu out
__device__ __align__(256) __nv_bfloat16 g_hlo[(size_t)MTOK * HID];

__device__ __align__(256) __nv_bfloat16 g_wqkvhi[(size_t)3 * DIMC * DIMC];
__device__ __align__(256) __nv_bfloat16 g_wqkvlo[(size_t)3 * DIMC * DIMC];
__device__ __align__(256) __nv_bfloat16 g_wprojhi[(size_t)DIMC * DIMC];
__device__ __align__(256) __nv_bfloat16 g_wprojlo[(size_t)DIMC * DIMC];
__device__ __align__(256) __nv_bfloat16 g_w1hi[(size_t)HID * DIMC];
__device__ __align__(256) __nv_bfloat16 g_w1lo[(size_t)HID * DIMC];
__device__ __align__(256) __nv_bfloat16 g_w2hi[(size_t)HID * DIMC];
__device__ __align__(256) __nv_bfloat16 g_w2lo[(size_t)HID * DIMC];
__device__ __align__(256) __nv_bfloat16 g_w3hi[(size_t)DIMC * HID];
__device__ __align__(256) __nv_bfloat16 g_w3lo[(size_t)DIMC * HID];

// Attention operands, per (b,h): Q/K [B*H][SEQ][64] hi/lo; Vt [B*H][64][SEQ]
__device__ __align__(256) __nv_bfloat16 g_qhi[(size_t)BATCH * NH * SEQ * HD];
__device__ __align__(256) __nv_bfloat16 g_qlo[(size_t)BATCH * NH * SEQ * HD];
__device__ __align__(256) __nv_bfloat16 g_khi[(size_t)BATCH * NH * SEQ * HD];
__device__ __align__(256) __nv_bfloat16 g_klo[(size_t)BATCH * NH * SEQ * HD];
__device__ __align__(256) __nv_bfloat16 g_vthi[(size_t)BATCH * NH * HD * SEQ];
__device__ __align__(256) __nv_bfloat16 g_vtlo[(size_t)BATCH * NH * HD * SEQ];

// ===========================================================================
// Helpers
// ===========================================================================
__device__ __forceinline__ unsigned smem_to_u32(const void* p) {
    unsigned a;
    asm("{ .reg .u64 t; cvta.to.shared.u64 t, %1; cvt.u32.u64 %0, t; }"
        : "=r"(a) : "l"(p));
    return a;
}
__device__ __forceinline__ void cp_async16(unsigned dst, const void* src) {
    asm volatile("cp.async.cg.shared.global [%0], [%1], 16;" :: "r"(dst), "l"(src));
}
__device__ __forceinline__ void cp_commit() {
    asm volatile("cp.async.commit_group;" ::: "memory");
}
template <int N>
__device__ __forceinline__ void cp_wait() {
    asm volatile("cp.async.wait_group %0;" :: "n"(N) : "memory");
}
__device__ __forceinline__ void ldm4(unsigned* r, unsigned addr) {
    asm volatile("ldmatrix.sync.aligned.m8n8.x4.shared.b16 {%0,%1,%2,%3}, [%4];"
        : "=r"(r[0]), "=r"(r[1]), "=r"(r[2]), "=r"(r[3]) : "r"(addr));
}
__device__ __forceinline__ void mma16816(float* d, const unsigned* a,
                                         unsigned b0, unsigned b1) {
    asm volatile(
        "mma.sync.aligned.m16n8k16.row.col.f32.bf16.bf16.f32 "
        "{%0,%1,%2,%3}, {%4,%5,%6,%7}, {%8,%9}, {%0,%1,%2,%3};"
        : "+f"(d[0]), "+f"(d[1]), "+f"(d[2]), "+f"(d[3])
        : "r"(a[0]), "r"(a[1]), "r"(a[2]), "r"(a[3]), "r"(b0), "r"(b1));
}
__device__ __forceinline__ unsigned pack_bf2(__nv_bfloat16 a, __nv_bfloat16 b) {
    unsigned short ua = *(unsigned short*)&a;
    unsigned short ub = *(unsigned short*)&b;
    return (unsigned)ua | ((unsigned)ub << 16);
}
__device__ __forceinline__ unsigned pack_hi2(float a, float b) {
    return pack_bf2(__float2bfloat16(a), __float2bfloat16(b));
}
__device__ __forceinline__ unsigned pack_lo2(float a, float b) {
    const __nv_bfloat16 ha = __float2bfloat16(a);
    const __nv_bfloat16 hb = __float2bfloat16(b);
    return pack_bf2(__float2bfloat16(a - __bfloat162float(ha)),
                    __float2bfloat16(b - __bfloat162float(hb)));
}
__device__ __forceinline__ unsigned swz128(int row, int c) {   // c: 16B chunk 0..7
    return (unsigned)(row * 128 + (((c ^ (row & 7))) << 4));
}

// ===========================================================================
// Vectorized split: fp32 -> separate bf16 hi + lo planes (4 elems/thread)
// ===========================================================================
__global__ void split4_kernel(const float* __restrict__ in,
                              __nv_bfloat16* __restrict__ hi,
                              __nv_bfloat16* __restrict__ lo, int n)
{
    const int i = (blockIdx.x * blockDim.x + threadIdx.x) * 4;
    if (i < n) {
        const float4 v = *(const float4*)(in + i);
        *(uint2*)(hi + i) = make_uint2(pack_hi2(v.x, v.y), pack_hi2(v.z, v.w));
        *(uint2*)(lo + i) = make_uint2(pack_lo2(v.x, v.y), pack_lo2(v.z, v.w));
    }
}

// ===========================================================================
// Non-redundant split-bf16 tensor-core NT GEMM:
//   C = Ah·Bh^T + Al·Bh^T + Ah·Bl^T (+ bias)
// BM=BN=128, BKP=64 physical k/stage, 3 stages x 64KB, loads-before-compute.
// 512 threads / 16 warps, warp grid 4x4, warp tile 32x32, mma m16n8k16.
// ===========================================================================
#define BM 128
#define BN 128
#define BKP 64
#define T_BYTES (128 * BKP * 2)       // 16 KB per tile
#define STG_BYTES (4 * T_BYTES)       // 64 KB
#define GSTAGES 3
#define GSMEM_SZ (GSTAGES * STG_BYTES)   // 192 KB

__global__ __launch_bounds__(512, 1) void gemm_mma_kernel(
    const __nv_bfloat16* __restrict__ Ahi, const __nv_bfloat16* __restrict__ Alo,
    const __nv_bfloat16* __restrict__ Bhi, const __nv_bfloat16* __restrict__ Blo,
    const float* __restrict__ bias,
    float* __restrict__ outf,
    __nv_bfloat16* __restrict__ outhi, __nv_bfloat16* __restrict__ outlo,
    int N, int K)
{
    extern __shared__ char sm[];
    const unsigned sbase = smem_to_u32(sm);
    const int tid = threadIdx.x;
    const int wid = tid >> 5;
    const int lane = tid & 31;
    const int m0 = blockIdx.y * BM;
    const int n0 = blockIdx.x * BN;
    const int mw = (wid & 3) * 32;     // warp m-offset (4 m-bands)
    const int nw = (wid >> 2) * 32;    // warp n-offset (4 n-bands)

    float acc[2][4][4];
#pragma unroll
    for (int a = 0; a < 2; a++)
#pragma unroll
        for (int b = 0; b < 4; b++)
#pragma unroll
            for (int c = 0; c < 4; c++) acc[a][b][c] = 0.0f;

#define G_LOADSTAGE(st, k0)                                                    \
    do {                                                                       \
        const unsigned s0 = sbase + (unsigned)(st) * STG_BYTES;                \
        _Pragma("unroll")                                                      \
        for (int i = 0; i < 2; i++) {                                          \
            const int idx = tid + i * 512;                                     \
            const int row = idx >> 3, ch = idx & 7;                            \
            const size_t ga = (size_t)(m0 + row) * K + (k0) + ch * 8;          \
            cp_async16(s0 + swz128(row, ch), Ahi + ga);                        \
            cp_async16(s0 + T_BYTES + swz128(row, ch), Alo + ga);              \
        }                                                                      \
        _Pragma("unroll")                                                      \
        for (int i = 0; i < 2; i++) {                                          \
            const int idx = tid + i * 512;                                     \
            const int row = idx >> 3, ch = idx & 7;                            \
            const size_t gb = (size_t)(n0 + row) * K + (k0) + ch * 8;          \
            cp_async16(s0 + 2 * T_BYTES + swz128(row, ch), Bhi + gb);          \
            cp_async16(s0 + 3 * T_BYTES + swz128(row, ch), Blo + gb);          \
        }                                                                      \
    } while (0)

    const int NKP = K / BKP;
    G_LOADSTAGE(0, 0);
    cp_commit();
    G_LOADSTAGE(1, BKP);
    cp_commit();

    int cur = 0, nxt = 2;
    for (int c = 0; c < NKP; c++) {
        cp_wait<1>();
        __syncthreads();
        if (c + 2 < NKP) { G_LOADSTAGE(nxt, (c + 2) * BKP); }
        cp_commit();

        const unsigned s0 = sbase + (unsigned)cur * STG_BYTES;

#pragma unroll
        for (int kk = 0; kk < 4; kk++) {
            unsigned ah[2][4], al[2][4], bh[2][4], bl[2][4];
#pragma unroll
            for (int mt = 0; mt < 2; mt++) {
                const int r = mw + mt * 16 + (lane & 15);
                const unsigned so = swz128(r, kk * 2 + (lane >> 4));
                ldm4(ah[mt], s0 + so);
                ldm4(al[mt], s0 + T_BYTES + so);
            }
#pragma unroll
            for (int ng = 0; ng < 2; ng++) {
                const int r = nw + ng * 16 + (lane & 7) + ((lane >> 4) << 3);
                const unsigned so = swz128(r, kk * 2 + ((lane >> 3) & 1));
                ldm4(bh[ng], s0 + 2 * T_BYTES + so);
                ldm4(bl[ng], s0 + 3 * T_BYTES + so);
            }
            // pass 1: Ah * Bh
#pragma unroll
            for (int mt = 0; mt < 2; mt++)
#pragma unroll
                for (int nt = 0; nt < 4; nt++)
                    mma16816(acc[mt][nt], ah[mt],
                             bh[nt >> 1][(nt & 1) * 2], bh[nt >> 1][(nt & 1) * 2 + 1]);
            // pass 2: Al * Bh
#pragma unroll
            for (int mt = 0; mt < 2; mt++)
#pragma unroll
                for (int nt = 0; nt < 4; nt++)
                    mma16816(acc[mt][nt], al[mt],
                             bh[nt >> 1][(nt & 1) * 2], bh[nt >> 1][(nt & 1) * 2 + 1]);
            // pass 3: Ah * Bl
#pragma unroll
            for (int mt = 0; mt < 2; mt++)
#pragma unroll
                for (int nt = 0; nt < 4; nt++)
                    mma16816(acc[mt][nt], ah[mt],
                             bl[nt >> 1][(nt & 1) * 2], bl[nt >> 1][(nt & 1) * 2 + 1]);
        }
        cur = (cur + 1 == GSTAGES) ? 0 : cur + 1;
        nxt = (nxt + 1 == GSTAGES) ? 0 : nxt + 1;
    }

    // Epilogue: warp covers 32 rows x 32 cols
#pragma unroll
    for (int mt = 0; mt < 2; mt++) {
#pragma unroll
        for (int nt = 0; nt < 4; nt++) {
            const int row0 = m0 + mw + mt * 16 + (lane >> 2);
            const int col  = n0 + nw + nt * 8 + (lane & 3) * 2;
            float bv0 = 0.0f, bv1 = 0.0f;
            if (bias != nullptr) { bv0 = bias[col]; bv1 = bias[col + 1]; }
#pragma unroll
            for (int h = 0; h < 2; h++) {
                const int row = row0 + h * 8;
                const float v0 = acc[mt][nt][h * 2 + 0] + bv0;
                const float v1 = acc[mt][nt][h * 2 + 1] + bv1;
                const size_t o = (size_t)row * N + col;
                if (outf != nullptr) {
                    *(float2*)&outf[o] = make_float2(v0, v1);
                }
                if (outhi != nullptr) {
                    *(unsigned*)&outhi[o] = pack_hi2(v0, v1);
                    *(unsigned*)&outlo[o] = pack_lo2(v0, v1);
                }
            }
        }
    }
#undef G_LOADSTAGE
}

// ===========================================================================
// Prep: rope + scale + hi/lo split for Q,K  ([B*H][SEQ][64] planes)
// Vectorized: each thread handles 2 adjacent j (float2 loads, 4B stores).
// ===========================================================================
__global__ void prep_qk_kernel(const float* __restrict__ qkv,
                               __nv_bfloat16* __restrict__ Qhi,
                               __nv_bfloat16* __restrict__ Qlo,
                               __nv_bfloat16* __restrict__ Khi,
                               __nv_bfloat16* __restrict__ Klo)
{
    const int idx = blockIdx.x * blockDim.x + threadIdx.x;   // 2^21
    const int jp = idx & 15;            // j-pair: j = 2*jp
    const int hh = (idx >> 4) & 15;
    const int n = (idx >> 8) & 2047;
    const int b = idx >> 19;
    const int j = jp * 2;

    const float f0 = expf(-(float)j * (9.210340371976184f / 32.0f));
    const float f1 = expf(-(float)(j + 1) * (9.210340371976184f / 32.0f));
    float sn0, cs0, sn1, cs1;
    sincosf((float)n * f0, &sn0, &cs0);
    sincosf((float)n * f1, &sn1, &cs1);

    const size_t base = ((size_t)(b * SEQ + n) * 3) * DIMC + hh * HD;
    const float2 qa = *(const float2*)(qkv + base + j);
    const float2 qb = *(const float2*)(qkv + base + j + 32);
    const float2 ka = *(const float2*)(qkv + base + DIMC + j);
    const float2 kb = *(const float2*)(qkv + base + DIMC + j + 32);

    const float qr0 = (qa.x * cs0 - qb.x * sn0) * 0.125f;
    const float qr1 = (qa.y * cs1 - qb.y * sn1) * 0.125f;
    const float qs0 = (qb.x * cs0 + qa.x * sn0) * 0.125f;
    const float qs1 = (qb.y * cs1 + qa.y * sn1) * 0.125f;
    const float kr0 = ka.x * cs0 - kb.x * sn0;
    const float kr1 = ka.y * cs1 - kb.y * sn1;
    const float ks0 = kb.x * cs0 + ka.x * sn0;
    const float ks1 = kb.y * cs1 + ka.y * sn1;

    const size_t off = ((size_t)(b * NH + hh) * SEQ + n) * HD;
    *(unsigned*)&Qhi[off + j]      = pack_hi2(qr0, qr1);
    *(unsigned*)&Qhi[off + j + 32] = pack_hi2(qs0, qs1);
    *(unsigned*)&Qlo[off + j]      = pack_lo2(qr0, qr1);
    *(unsigned*)&Qlo[off + j + 32] = pack_lo2(qs0, qs1);
    *(unsigned*)&Khi[off + j]      = pack_hi2(kr0, kr1);
    *(unsigned*)&Khi[off + j + 32] = pack_hi2(ks0, ks1);
    *(unsigned*)&Klo[off + j]      = pack_lo2(kr0, kr1);
    *(unsigned*)&Klo[off + j + 32] = pack_lo2(ks0, ks1);
}

// ===========================================================================
// Prep: V transpose + split  ([B*H][64][SEQ] hi/lo)
// ===========================================================================
__global__ __launch_bounds__(256) void prep_v_kernel(
    const float* __restrict__ qkv,
    __nv_bfloat16* __restrict__ Vthi, __nv_bfloat16* __restrict__ Vtlo)
{
    __shared__ float ts[64][65];
    const int tid = threadIdx.x;
    const int tile = blockIdx.x;        // bh*32 + ntile
    const int bh = tile >> 5;
    const int k0 = (tile & 31) * 64;
    const int b = bh >> 4, hh = bh & 15;

    for (int i = tid; i < 4096; i += 256) {
        const int r = i >> 6, c = i & 63;
        ts[c][r] = qkv[((size_t)(b * SEQ + k0 + r) * 3 + 2) * DIMC + hh * HD + c];
    }
    __syncthreads();
    for (int i = tid; i < 4096; i += 256) {
        const int d = i >> 6, n = i & 63;
        const float v = ts[d][n];
        const __nv_bfloat16 h = __float2bfloat16(v);
        const size_t off = ((size_t)bh * HD + d) * SEQ + k0 + n;
        Vthi[off] = h;
        Vtlo[off] = __float2bfloat16(v - __bfloat162float(h));
    }
}

// ===========================================================================
// Tensor-core flash attention (non-causal), non-redundant split-bf16.
// Block: 128 q rows x 8 warps; 64-key tiles; 3-stage pipeline (128 KB smem).
//   S = Qh·Kh^T + Ql·Kh^T + Qh·Kl^T  (fragments hoisted per k-step)
//   O += Phi·Vhi + Plo·Vhi + Phi·Vlo
// ===========================================================================
#define AQ 128
#define AK 64
#define ANT (SEQ / AK)          // 32 key tiles
#define ASM_QH 0
#define ASM_QL 16384
#define ASM_STG 32768
#define ATILE 8192
#define ASTG_SZ (4 * ATILE)     // 32 KB
#define ASTAGES 3
#define ASM_TOTAL (ASM_STG + ASTAGES * ASTG_SZ)   // 131072

__global__ __launch_bounds__(256, 1) void attn_mma_kernel(
    const __nv_bfloat16* __restrict__ Qhi, const __nv_bfloat16* __restrict__ Qlo,
    const __nv_bfloat16* __restrict__ Khi, const __nv_bfloat16* __restrict__ Klo,
    const __nv_bfloat16* __restrict__ Vthi, const __nv_bfloat16* __restrict__ Vtlo,
    __nv_bfloat16* __restrict__ outhi, __nv_bfloat16* __restrict__ outlo)
{
    extern __shared__ char sm[];
    const unsigned sb = smem_to_u32(sm);
    const int tid = threadIdx.x, wid = tid >> 5, lane = tid & 31;
    const int n0 = blockIdx.x * AQ;
    const int bh = blockIdx.y;
    const int b = bh >> 4, hh = bh & 15;
    const size_t qkrow0 = (size_t)bh * SEQ;

    // Stage layout: +0 Kh, +8K Kl, +16K Vh, +24K Vl (64 rows x 128B each)
#define A_LOADSTAGE(buf, k0)                                                  \
    do {                                                                      \
        const unsigned s0 = sb + ASM_STG + (unsigned)(buf) * ASTG_SZ;         \
        for (int i = tid; i < 512; i += 256) {                                \
            const int row = i >> 3, ch = i & 7;                               \
            const size_t gk = (qkrow0 + (k0) + row) * HD + ch * 8;            \
            cp_async16(s0 + swz128(row, ch), Khi + gk);                       \
            cp_async16(s0 + ATILE + swz128(row, ch), Klo + gk);               \
            const size_t gv = ((size_t)bh * HD + row) * SEQ + (k0) + ch * 8;  \
            cp_async16(s0 + 2 * ATILE + swz128(row, ch), Vthi + gv);          \
            cp_async16(s0 + 3 * ATILE + swz128(row, ch), Vtlo + gv);          \
        }                                                                     \
    } while (0)

    // Q tiles (hi + lo) in group 0 together with stage 0
    for (int i = tid; i < 1024; i += 256) {
        const int row = i >> 3, ch = i & 7;
        const size_t gq = (qkrow0 + n0 + row) * HD + ch * 8;
        cp_async16(sb + ASM_QH + swz128(row, ch), Qhi + gq);
        cp_async16(sb + ASM_QL + swz128(row, ch), Qlo + gq);
    }
    A_LOADSTAGE(0, 0);
    cp_commit();
    A_LOADSTAGE(1, AK);
    cp_commit();

    float m0 = -1e30f, m1 = -1e30f, l0 = 0.0f, l1 = 0.0f;
    float o[8][4];
#pragma unroll
    for (int nt = 0; nt < 8; nt++)
#pragma unroll
        for (int c = 0; c < 4; c++) o[nt][c] = 0.0f;

    const int ar = wid * 16 + (lane & 15);           // A ldmatrix row
    const int brq = (lane & 7) + ((lane >> 4) << 3); // B ldmatrix row base
    const int bcq = (lane >> 3) & 1;                 // B chunk phase

    int cur = 0, nxt = 2;
    for (int t = 0; t < ANT; t++) {
        cp_wait<1>();
        __syncthreads();
        if (t + 2 < ANT) { A_LOADSTAGE(nxt, (t + 2) * AK); }
        cp_commit();

        const unsigned s0  = sb + ASM_STG + (unsigned)cur * ASTG_SZ;
        const unsigned s_vh = s0 + 2 * ATILE, s_vl = s0 + 3 * ATILE;

        // ---- S: hoisted fragments, 3 passes per k-step
        float p[8][4];
#pragma unroll
        for (int nt = 0; nt < 8; nt++)
#pragma unroll
            for (int c = 0; c < 4; c++) p[nt][c] = 0.0f;

#pragma unroll
        for (int kk = 0; kk < 4; kk++) {
            unsigned ah[4], al[4];
            const unsigned aso = swz128(ar, kk * 2 + (lane >> 4));
            ldm4(ah, sb + ASM_QH + aso);
            ldm4(al, sb + ASM_QL + aso);
            unsigned bhf[4][4], blf[4][4];
#pragma unroll
            for (int ng = 0; ng < 4; ng++) {
                const unsigned bso = swz128(ng * 16 + brq, kk * 2 + bcq);
                ldm4(bhf[ng], s0 + bso);
                ldm4(blf[ng], s0 + ATILE + bso);
            }
#pragma unroll
            for (int nt = 0; nt < 8; nt++)
                mma16816(p[nt], ah, bhf[nt >> 1][(nt & 1) * 2],
                         bhf[nt >> 1][(nt & 1) * 2 + 1]);
#pragma unroll
            for (int nt = 0; nt < 8; nt++)
                mma16816(p[nt], al, bhf[nt >> 1][(nt & 1) * 2],
                         bhf[nt >> 1][(nt & 1) * 2 + 1]);
#pragma unroll
            for (int nt = 0; nt < 8; nt++)
                mma16816(p[nt], ah, blf[nt >> 1][(nt & 1) * 2],
                         blf[nt >> 1][(nt & 1) * 2 + 1]);
        }

        // ---- online softmax (rows g=lane>>2 and g+8; quad reduction)
        float t0 = -1e30f, t1 = -1e30f;
#pragma unroll
        for (int nt = 0; nt < 8; nt++) {
            t0 = fmaxf(t0, fmaxf(p[nt][0], p[nt][1]));
            t1 = fmaxf(t1, fmaxf(p[nt][2], p[nt][3]));
        }
        t0 = fmaxf(t0, __shfl_xor_sync(0xffffffffu, t0, 1));
        t0 = fmaxf(t0, __shfl_xor_sync(0xffffffffu, t0, 2));
        t1 = fmaxf(t1, __shfl_xor_sync(0xffffffffu, t1, 1));
        t1 = fmaxf(t1, __shfl_xor_sync(0xffffffffu, t1, 2));
        const float mn0 = fmaxf(m0, t0), mn1 = fmaxf(m1, t1);
        const float al0 = __expf(m0 - mn0), al1 = __expf(m1 - mn1);
        m0 = mn0; m1 = mn1;
        float s0s = 0.0f, s1s = 0.0f;
#pragma unroll
        for (int nt = 0; nt < 8; nt++) {
            p[nt][0] = __expf(p[nt][0] - mn0);
            p[nt][1] = __expf(p[nt][1] - mn0);
            p[nt][2] = __expf(p[nt][2] - mn1);
            p[nt][3] = __expf(p[nt][3] - mn1);
            s0s += p[nt][0] + p[nt][1];
            s1s += p[nt][2] + p[nt][3];
        }
        s0s += __shfl_xor_sync(0xffffffffu, s0s, 1);
        s0s += __shfl_xor_sync(0xffffffffu, s0s, 2);
        s1s += __shfl_xor_sync(0xffffffffu, s1s, 1);
        s1s += __shfl_xor_sync(0xffffffffu, s1s, 2);
        l0 = l0 * al0 + s0s;
        l1 = l1 * al1 + s1s;
#pragma unroll
        for (int nt = 0; nt < 8; nt++) {
            o[nt][0] *= al0; o[nt][1] *= al0;
            o[nt][2] *= al1; o[nt][3] *= al1;
        }

        // ---- O += P @ V  (3 split terms)
#pragma unroll
        for (int kt = 0; kt < 4; kt++) {
            unsigned phi[4], plo[4];
            phi[0] = pack_hi2(p[2 * kt][0], p[2 * kt][1]);
            phi[1] = pack_hi2(p[2 * kt][2], p[2 * kt][3]);
            phi[2] = pack_hi2(p[2 * kt + 1][0], p[2 * kt + 1][1]);
            phi[3] = pack_hi2(p[2 * kt + 1][2], p[2 * kt + 1][3]);
            plo[0] = pack_lo2(p[2 * kt][0], p[2 * kt][1]);
            plo[1] = pack_lo2(p[2 * kt][2], p[2 * kt][3]);
            plo[2] = pack_lo2(p[2 * kt + 1][0], p[2 * kt + 1][1]);
            plo[3] = pack_lo2(p[2 * kt + 1][2], p[2 * kt + 1][3]);
#pragma unroll
            for (int ng = 0; ng < 4; ng++) {
                unsigned bhf[4], blf[4];
                const unsigned bso = swz128(ng * 16 + brq, kt * 2 + bcq);
                ldm4(bhf, s_vh + bso);
                ldm4(blf, s_vl + bso);
                mma16816(o[2 * ng],     phi, bhf[0], bhf[1]);
                mma16816(o[2 * ng + 1], phi, bhf[2], bhf[3]);
                mma16816(o[2 * ng],     plo, bhf[0], bhf[1]);
                mma16816(o[2 * ng + 1], plo, bhf[2], bhf[3]);
                mma16816(o[2 * ng],     phi, blf[0], blf[1]);
                mma16816(o[2 * ng + 1], phi, blf[2], blf[3]);
            }
        }
        cur = (cur + 1 == ASTAGES) ? 0 : cur + 1;
        nxt = (nxt + 1 == ASTAGES) ? 0 : nxt + 1;
    }

    // ---- epilogue: normalize, write hi/lo planes [MTOK][DIMC]
    const float il0 = 1.0f / l0, il1 = 1.0f / l1;
    const int g = lane >> 2;
    const int row0 = n0 + wid * 16 + g;
    const int row1 = row0 + 8;
#pragma unroll
    for (int nt = 0; nt < 8; nt++) {
        const int d = nt * 8 + (lane & 3) * 2;
        const float x0 = o[nt][0] * il0, x1 = o[nt][1] * il0;
        const float y0 = o[nt][2] * il1, y1 = o[nt][3] * il1;
        const size_t b0 = (size_t)(b * SEQ + row0) * DIMC + hh * HD + d;
        const size_t b1 = (size_t)(b * SEQ + row1) * DIMC + hh * HD + d;
        *(unsigned*)&outhi[b0] = pack_hi2(x0, x1);
        *(unsigned*)&outlo[b0] = pack_lo2(x0, x1);
        *(unsigned*)&outhi[b1] = pack_hi2(y0, y1);
        *(unsigned*)&outlo[b1] = pack_lo2(y0, y1);
    }
#undef A_LOADSTAGE
}

// ===========================================================================
// SwiGLU elementwise -> hi/lo planes (4 elems/thread)
// ===========================================================================
__global__ void silu_split4_kernel(const float* __restrict__ x1,
                                   const float* __restrict__ x2,
                                   __nv_bfloat16* __restrict__ hi,
                                   __nv_bfloat16* __restrict__ lo, int n)
{
    const int i = (blockIdx.x * blockDim.x + threadIdx.x) * 4;
    if (i < n) {
        const float4 a = *(const float4*)(x1 + i);
        const float4 b = *(const float4*)(x2 + i);
        const float v0 = (a.x / (1.0f + expf(-a.x))) * b.x;
        const float v1 = (a.y / (1.0f + expf(-a.y))) * b.y;
        const float v2 = (a.z / (1.0f + expf(-a.z))) * b.z;
        const float v3 = (a.w / (1.0f + expf(-a.w))) * b.w;
        *(uint2*)(hi + i) = make_uint2(pack_hi2(v0, v1), pack_hi2(v2, v3));
        *(uint2*)(lo + i) = make_uint2(pack_lo2(v0, v1), pack_lo2(v2, v3));
    }
}

// ===========================================================================
// kernel_launch  (my launch index 3 = QKV GEMM = ncu capture position)
// ===========================================================================
extern "C" void kernel_launch(void* const* d_in, const int* in_sizes, int n_in,
                              void* d_out, int out_size)
{
    const float* x      = (const float*)d_in[0];
    const float* qkv_w  = (const float*)d_in[1];
    const float* proj_w = (const float*)d_in[2];
    const float* proj_b = (const float*)d_in[3];
    const float* w1_w   = (const float*)d_in[4];
    const float* w1_b   = (const float*)d_in[5];
    const float* w2_w   = (const float*)d_in[6];
    const float* w2_b   = (const float*)d_in[7];
    const float* w3_w   = (const float*)d_in[8];
    const float* w3_b   = (const float*)d_in[9];
    float* out = (float*)d_out;

    cudaFuncSetAttribute(gemm_mma_kernel,
                         cudaFuncAttributeMaxDynamicSharedMemorySize, GSMEM_SZ);
    cudaFuncSetAttribute(attn_mma_kernel,
                         cudaFuncAttributeMaxDynamicSharedMemorySize, ASM_TOTAL);

    float *qkv, *x1, *x2;
    cudaGetSymbolAddress((void**)&qkv, g_qkv);
    cudaGetSymbolAddress((void**)&x1,  g_x1);
    cudaGetSymbolAddress((void**)&x2,  g_x2);
    __nv_bfloat16 *xhi, *xlo, *ahi, *alo, *phi, *plo, *hhi, *hlo;
    __nv_bfloat16 *wqh, *wql, *wph, *wpl, *w1h, *w1l, *w2h, *w2l, *w3h, *w3l;
    __nv_bfloat16 *qhi, *qlo, *khi, *klo, *vthi, *vtlo;
    cudaGetSymbolAddress((void**)&xhi, g_xhi);  cudaGetSymbolAddress((void**)&xlo, g_xlo);
    cudaGetSymbolAddress((void**)&ahi, g_ahi);  cudaGetSymbolAddress((void**)&alo, g_alo);
    cudaGetSymbolAddress((void**)&phi, g_phi);  cudaGetSymbolAddress((void**)&plo, g_plo);
    cudaGetSymbolAddress((void**)&hhi, g_hhi);  cudaGetSymbolAddress((void**)&hlo, g_hlo);
    cudaGetSymbolAddress((void**)&wqh, g_wqkvhi);  cudaGetSymbolAddress((void**)&wql, g_wqkvlo);
    cudaGetSymbolAddress((void**)&wph, g_wprojhi); cudaGetSymbolAddress((void**)&wpl, g_wprojlo);
    cudaGetSymbolAddress((void**)&w1h, g_w1hi);    cudaGetSymbolAddress((void**)&w1l, g_w1lo);
    cudaGetSymbolAddress((void**)&w2h, g_w2hi);    cudaGetSymbolAddress((void**)&w2l, g_w2lo);
    cudaGetSymbolAddress((void**)&w3h, g_w3hi);    cudaGetSymbolAddress((void**)&w3l, g_w3lo);
    cudaGetSymbolAddress((void**)&qhi, g_qhi);  cudaGetSymbolAddress((void**)&qlo, g_qlo);
    cudaGetSymbolAddress((void**)&khi, g_khi);  cudaGetSymbolAddress((void**)&klo, g_klo);
    cudaGetSymbolAddress((void**)&vthi, g_vthi); cudaGetSymbolAddress((void**)&vtlo, g_vtlo);

    // idx 0-2: splits needed for QKV GEMM (+ proj weights)
    split4_kernel<<<(MTOK * DIMC) / 1024, 256>>>(x, xhi, xlo, MTOK * DIMC);
    split4_kernel<<<(3 * DIMC * DIMC) / 1024, 256>>>(qkv_w, wqh, wql, 3 * DIMC * DIMC);
    split4_kernel<<<(DIMC * DIMC) / 1024, 256>>>(proj_w, wph, wpl, DIMC * DIMC);

    // idx 3: QKV projection -> fp32   (ncu capture position)
    gemm_mma_kernel<<<dim3(3 * DIMC / BN, MTOK / BM), 512, GSMEM_SZ>>>(
        xhi, xlo, wqh, wql, nullptr, qkv, nullptr, nullptr, 3 * DIMC, DIMC);

    // Rope + split prep for attention operands
    prep_qk_kernel<<<(BATCH * SEQ * NH * 16) / 256, 256>>>(qkv, qhi, qlo, khi, klo);
    prep_v_kernel<<<BATCH * NH * (SEQ / 64), 256>>>(qkv, vthi, vtlo);

    // Tensor-core attention -> hi/lo planes
    attn_mma_kernel<<<dim3(SEQ / AQ, BATCH * NH), 256, ASM_TOTAL>>>(
        qhi, qlo, khi, klo, vthi, vtlo, ahi, alo);

    // Output projection (+bias) -> hi/lo planes
    gemm_mma_kernel<<<dim3(DIMC / BN, MTOK / BM), 512, GSMEM_SZ>>>(
        ahi, alo, wph, wpl, proj_b, nullptr, phi, plo, DIMC, DIMC);

    // MLP up projections -> fp32
    split4_kernel<<<(HID * DIMC) / 1024, 256>>>(w1_w, w1h, w1l, HID * DIMC);
    gemm_mma_kernel<<<dim3(HID / BN, MTOK / BM), 512, GSMEM_SZ>>>(
        phi, plo, w1h, w1l, w1_b, x1, nullptr, nullptr, HID, DIMC);
    split4_kernel<<<(HID * DIMC) / 1024, 256>>>(w2_w, w2h, w2l, HID * DIMC);
    gemm_mma_kernel<<<dim3(HID / BN, MTOK / BM), 512, GSMEM_SZ>>>(
        phi, plo, w2h, w2l, w2_b, x2, nullptr, nullptr, HID, DIMC);

    // SwiGLU -> hi/lo planes
    silu_split4_kernel<<<(MTOK * HID) / 1024, 256>>>(x1, x2, hhi, hlo, MTOK * HID);

    // w3 split + down projection -> fp32 out
    split4_kernel<<<(DIMC * HID) / 1024, 256>>>(w3_w, w3h, w3l, DIMC * HID);
    gemm_mma_kernel<<<dim3(DIMC / BN, MTOK / BM), 512, GSMEM_SZ>>>(
        hhi, hlo, w3h, w3l, w3_b, out, nullptr, nullptr, DIMC, HID);
}

// round 14
// speedup vs baseline: 1.0549x; 1.0549x over previous
#include <cuda_runtime.h>
#include <cuda_bf16.h>
#include <math.h>

// Problem constants
#define BATCH 4
#define SEQ   2048
#define DIMC  1024
#define NH    16
#define HD    64
#define HID   2048
#define MTOK  (BATCH * SEQ)   // 8192 tokens

// ===========================================================================
// Scratch (static device globals; allocations forbidden)
// ===========================================================================
__device__ float g_qkv[(size_t)MTOK * 3 * DIMC];   // fp32 qkv (pre-rope)
__device__ float g_x1[(size_t)MTOK * HID];
__device__ float g_x2[(size_t)MTOK * HID];

// Separate hi/lo bf16 planes (non-redundant split scheme)
__device__ __align__(256) __nv_bfloat16 g_xhi[(size_t)MTOK * DIMC];
__device__ __align__(256) __nv_bfloat16 g_xlo[(size_t)MTOK * DIMC];
__device__ __align__(256) __nv_bfloat16 g_ahi[(size_t)MTOK * DIMC];   // attn out
__device__ __align__(256) __nv_bfloat16 g_alo[(size_t)MTOK * DIMC];
__device__ __align__(256) __nv_bfloat16 g_phi[(size_t)MTOK * DIMC];   // proj out
__device__ __align__(256) __nv_bfloat16 g_plo[(size_t)MTOK * DIMC];
__device__ __align__(256) __nv_bfloat16 g_hhi[(size_t)MTOK * HID];    // swiglu out
__device__ __align__(256) __nv_bfloat16 g_hlo[(size_t)MTOK * HID];

__device__ __align__(256) __nv_bfloat16 g_wqkvhi[(size_t)3 * DIMC * DIMC];
__device__ __align__(256) __nv_bfloat16 g_wqkvlo[(size_t)3 * DIMC * DIMC];
__device__ __align__(256) __nv_bfloat16 g_wprojhi[(size_t)DIMC * DIMC];
__device__ __align__(256) __nv_bfloat16 g_wprojlo[(size_t)DIMC * DIMC];
__device__ __align__(256) __nv_bfloat16 g_w1hi[(size_t)HID * DIMC];
__device__ __align__(256) __nv_bfloat16 g_w1lo[(size_t)HID * DIMC];
__device__ __align__(256) __nv_bfloat16 g_w2hi[(size_t)HID * DIMC];
__device__ __align__(256) __nv_bfloat16 g_w2lo[(size_t)HID * DIMC];
__device__ __align__(256) __nv_bfloat16 g_w3hi[(size_t)DIMC * HID];
__device__ __align__(256) __nv_bfloat16 g_w3lo[(size_t)DIMC * HID];

// Attention operands, per (b,h): Q/K [B*H][SEQ][64] hi/lo; Vt [B*H][64][SEQ]
__device__ __align__(256) __nv_bfloat16 g_qhi[(size_t)BATCH * NH * SEQ * HD];
__device__ __align__(256) __nv_bfloat16 g_qlo[(size_t)BATCH * NH * SEQ * HD];
__device__ __align__(256) __nv_bfloat16 g_khi[(size_t)BATCH * NH * SEQ * HD];
__device__ __align__(256) __nv_bfloat16 g_klo[(size_t)BATCH * NH * SEQ * HD];
__device__ __align__(256) __nv_bfloat16 g_vthi[(size_t)BATCH * NH * HD * SEQ];
__device__ __align__(256) __nv_bfloat16 g_vtlo[(size_t)BATCH * NH * HD * SEQ];

// ===========================================================================
// Helpers
// ===========================================================================
__device__ __forceinline__ unsigned smem_to_u32(const void* p) {
    unsigned a;
    asm("{ .reg .u64 t; cvta.to.shared.u64 t, %1; cvt.u32.u64 %0, t; }"
        : "=r"(a) : "l"(p));
    return a;
}
__device__ __forceinline__ void cp_async16(unsigned dst, const void* src) {
    asm volatile("cp.async.cg.shared.global [%0], [%1], 16;" :: "r"(dst), "l"(src));
}
__device__ __forceinline__ void cp_commit() {
    asm volatile("cp.async.commit_group;" ::: "memory");
}
template <int N>
__device__ __forceinline__ void cp_wait() {
    asm volatile("cp.async.wait_group %0;" :: "n"(N) : "memory");
}
__device__ __forceinline__ void ldm4(unsigned* r, unsigned addr) {
    asm volatile("ldmatrix.sync.aligned.m8n8.x4.shared.b16 {%0,%1,%2,%3}, [%4];"
        : "=r"(r[0]), "=r"(r[1]), "=r"(r[2]), "=r"(r[3]) : "r"(addr));
}
__device__ __forceinline__ void mma16816(float* d, const unsigned* a,
                                         unsigned b0, unsigned b1) {
    asm volatile(
        "mma.sync.aligned.m16n8k16.row.col.f32.bf16.bf16.f32 "
        "{%0,%1,%2,%3}, {%4,%5,%6,%7}, {%8,%9}, {%0,%1,%2,%3};"
        : "+f"(d[0]), "+f"(d[1]), "+f"(d[2]), "+f"(d[3])
        : "r"(a[0]), "r"(a[1]), "r"(a[2]), "r"(a[3]), "r"(b0), "r"(b1));
}
__device__ __forceinline__ unsigned pack_bf2(__nv_bfloat16 a, __nv_bfloat16 b) {
    unsigned short ua = *(unsigned short*)&a;
    unsigned short ub = *(unsigned short*)&b;
    return (unsigned)ua | ((unsigned)ub << 16);
}
__device__ __forceinline__ unsigned pack_hi2(float a, float b) {
    return pack_bf2(__float2bfloat16(a), __float2bfloat16(b));
}
__device__ __forceinline__ unsigned pack_lo2(float a, float b) {
    const __nv_bfloat16 ha = __float2bfloat16(a);
    const __nv_bfloat16 hb = __float2bfloat16(b);
    return pack_bf2(__float2bfloat16(a - __bfloat162float(ha)),
                    __float2bfloat16(b - __bfloat162float(hb)));
}
__device__ __forceinline__ unsigned swz128(int row, int c) {   // c: 16B chunk 0..7
    return (unsigned)(row * 128 + (((c ^ (row & 7))) << 4));
}

// ===========================================================================
// Vectorized split: fp32 -> separate bf16 hi + lo planes (4 elems/thread)
// ===========================================================================
__global__ void split4_kernel(const float* __restrict__ in,
                              __nv_bfloat16* __restrict__ hi,
                              __nv_bfloat16* __restrict__ lo, int n)
{
    const int i = (blockIdx.x * blockDim.x + threadIdx.x) * 4;
    if (i < n) {
        const float4 v = *(const float4*)(in + i);
        *(uint2*)(hi + i) = make_uint2(pack_hi2(v.x, v.y), pack_hi2(v.z, v.w));
        *(uint2*)(lo + i) = make_uint2(pack_lo2(v.x, v.y), pack_lo2(v.z, v.w));
    }
}

// ===========================================================================
// Non-redundant split-bf16 tensor-core NT GEMM:
//   C = Ah·Bh^T + Al·Bh^T + Ah·Bl^T (+ bias)
// BM=64, BN=128, BKP=64; 2 stages x 48KB = 96KB -> 2 CTAs/SM (bubble cover).
// 256 threads / 8 warps, warp grid 2(m) x 4(n), warp tile 32x32.
// ===========================================================================
#define BM 64
#define BN 128
#define BKP 64
#define TA_BYTES (BM * BKP * 2)          // 8 KB per A plane
#define TB_BYTES (BN * BKP * 2)          // 16 KB per B plane
#define OFF_AL  TA_BYTES                 // 8192
#define OFF_BH  (2 * TA_BYTES)           // 16384
#define OFF_BL  (2 * TA_BYTES + TB_BYTES) // 32768
#define STG_BYTES (2 * TA_BYTES + 2 * TB_BYTES)  // 48 KB
#define GSMEM_SZ (2 * STG_BYTES)         // 96 KB

__global__ __launch_bounds__(256, 2) void gemm_mma_kernel(
    const __nv_bfloat16* __restrict__ Ahi, const __nv_bfloat16* __restrict__ Alo,
    const __nv_bfloat16* __restrict__ Bhi, const __nv_bfloat16* __restrict__ Blo,
    const float* __restrict__ bias,
    float* __restrict__ outf,
    __nv_bfloat16* __restrict__ outhi, __nv_bfloat16* __restrict__ outlo,
    int N, int K)
{
    extern __shared__ char sm[];
    const unsigned sbase = smem_to_u32(sm);
    const int tid = threadIdx.x;
    const int wid = tid >> 5;
    const int lane = tid & 31;
    const int m0 = blockIdx.y * BM;
    const int n0 = blockIdx.x * BN;
    const int mw = (wid & 1) * 32;     // warp m-offset (2 m-bands)
    const int nw = (wid >> 1) * 32;    // warp n-offset (4 n-bands)

    float acc[2][4][4];
#pragma unroll
    for (int a = 0; a < 2; a++)
#pragma unroll
        for (int b = 0; b < 4; b++)
#pragma unroll
            for (int c = 0; c < 4; c++) acc[a][b][c] = 0.0f;

#define G_LOADSTAGE(st, k0)                                                    \
    do {                                                                       \
        const unsigned s0 = sbase + (unsigned)(st) * STG_BYTES;                \
        _Pragma("unroll")                                                      \
        for (int i = 0; i < 2; i++) {                                          \
            const int idx = tid + i * 256;                                     \
            const int row = idx >> 3, ch = idx & 7;                            \
            const size_t ga = (size_t)(m0 + row) * K + (k0) + ch * 8;          \
            cp_async16(s0 + swz128(row, ch), Ahi + ga);                        \
            cp_async16(s0 + OFF_AL + swz128(row, ch), Alo + ga);               \
        }                                                                      \
        _Pragma("unroll")                                                      \
        for (int i = 0; i < 4; i++) {                                          \
            const int idx = tid + i * 256;                                     \
            const int row = idx >> 3, ch = idx & 7;                            \
            const size_t gb = (size_t)(n0 + row) * K + (k0) + ch * 8;          \
            cp_async16(s0 + OFF_BH + swz128(row, ch), Bhi + gb);               \
            cp_async16(s0 + OFF_BL + swz128(row, ch), Blo + gb);               \
        }                                                                      \
    } while (0)

    const int NKP = K / BKP;
    G_LOADSTAGE(0, 0);
    cp_commit();
    G_LOADSTAGE(1, BKP);
    cp_commit();

    for (int c = 0; c < NKP; c++) {
        if (c < NKP - 1) cp_wait<1>(); else cp_wait<0>();
        __syncthreads();
        const unsigned s0 = sbase + (unsigned)(c & 1) * STG_BYTES;

#pragma unroll
        for (int kk = 0; kk < 4; kk++) {
            unsigned ah[2][4], al[2][4], bh[2][4], bl[2][4];
#pragma unroll
            for (int mt = 0; mt < 2; mt++) {
                const int r = mw + mt * 16 + (lane & 15);
                const unsigned so = swz128(r, kk * 2 + (lane >> 4));
                ldm4(ah[mt], s0 + so);
                ldm4(al[mt], s0 + OFF_AL + so);
            }
#pragma unroll
            for (int ng = 0; ng < 2; ng++) {
                const int r = nw + ng * 16 + (lane & 7) + ((lane >> 4) << 3);
                const unsigned so = swz128(r, kk * 2 + ((lane >> 3) & 1));
                ldm4(bh[ng], s0 + OFF_BH + so);
                ldm4(bl[ng], s0 + OFF_BL + so);
            }
            // pass 1: Ah * Bh
#pragma unroll
            for (int mt = 0; mt < 2; mt++)
#pragma unroll
                for (int nt = 0; nt < 4; nt++)
                    mma16816(acc[mt][nt], ah[mt],
                             bh[nt >> 1][(nt & 1) * 2], bh[nt >> 1][(nt & 1) * 2 + 1]);
            // pass 2: Al * Bh
#pragma unroll
            for (int mt = 0; mt < 2; mt++)
#pragma unroll
                for (int nt = 0; nt < 4; nt++)
                    mma16816(acc[mt][nt], al[mt],
                             bh[nt >> 1][(nt & 1) * 2], bh[nt >> 1][(nt & 1) * 2 + 1]);
            // pass 3: Ah * Bl
#pragma unroll
            for (int mt = 0; mt < 2; mt++)
#pragma unroll
                for (int nt = 0; nt < 4; nt++)
                    mma16816(acc[mt][nt], ah[mt],
                             bl[nt >> 1][(nt & 1) * 2], bl[nt >> 1][(nt & 1) * 2 + 1]);
        }
        __syncthreads();
        if (c + 2 < NKP) {
            G_LOADSTAGE((c & 1), (c + 2) * BKP);
            cp_commit();
        }
    }

    // Epilogue: warp covers 32 rows x 32 cols
#pragma unroll
    for (int mt = 0; mt < 2; mt++) {
#pragma unroll
        for (int nt = 0; nt < 4; nt++) {
            const int row0 = m0 + mw + mt * 16 + (lane >> 2);
            const int col  = n0 + nw + nt * 8 + (lane & 3) * 2;
            float bv0 = 0.0f, bv1 = 0.0f;
            if (bias != nullptr) { bv0 = bias[col]; bv1 = bias[col + 1]; }
#pragma unroll
            for (int h = 0; h < 2; h++) {
                const int row = row0 + h * 8;
                const float v0 = acc[mt][nt][h * 2 + 0] + bv0;
                const float v1 = acc[mt][nt][h * 2 + 1] + bv1;
                const size_t o = (size_t)row * N + col;
                if (outf != nullptr) {
                    *(float2*)&outf[o] = make_float2(v0, v1);
                }
                if (outhi != nullptr) {
                    *(unsigned*)&outhi[o] = pack_hi2(v0, v1);
                    *(unsigned*)&outlo[o] = pack_lo2(v0, v1);
                }
            }
        }
    }
#undef G_LOADSTAGE
}

// ===========================================================================
// Prep: rope + scale + hi/lo split for Q,K  ([B*H][SEQ][64] planes)
// ===========================================================================
__global__ void prep_qk_kernel(const float* __restrict__ qkv,
                               __nv_bfloat16* __restrict__ Qhi,
                               __nv_bfloat16* __restrict__ Qlo,
                               __nv_bfloat16* __restrict__ Khi,
                               __nv_bfloat16* __restrict__ Klo)
{
    const int idx = blockIdx.x * blockDim.x + threadIdx.x;   // 2^21
    const int jp = idx & 15;            // j-pair: j = 2*jp
    const int hh = (idx >> 4) & 15;
    const int n = (idx >> 8) & 2047;
    const int b = idx >> 19;
    const int j = jp * 2;

    const float f0 = expf(-(float)j * (9.210340371976184f / 32.0f));
    const float f1 = expf(-(float)(j + 1) * (9.210340371976184f / 32.0f));
    float sn0, cs0, sn1, cs1;
    sincosf((float)n * f0, &sn0, &cs0);
    sincosf((float)n * f1, &sn1, &cs1);

    const size_t base = ((size_t)(b * SEQ + n) * 3) * DIMC + hh * HD;
    const float2 qa = *(const float2*)(qkv + base + j);
    const float2 qb = *(const float2*)(qkv + base + j + 32);
    const float2 ka = *(const float2*)(qkv + base + DIMC + j);
    const float2 kb = *(const float2*)(qkv + base + DIMC + j + 32);

    const float qr0 = (qa.x * cs0 - qb.x * sn0) * 0.125f;
    const float qr1 = (qa.y * cs1 - qb.y * sn1) * 0.125f;
    const float qs0 = (qb.x * cs0 + qa.x * sn0) * 0.125f;
    const float qs1 = (qb.y * cs1 + qa.y * sn1) * 0.125f;
    const float kr0 = ka.x * cs0 - kb.x * sn0;
    const float kr1 = ka.y * cs1 - kb.y * sn1;
    const float ks0 = kb.x * cs0 + ka.x * sn0;
    const float ks1 = kb.y * cs1 + ka.y * sn1;

    const size_t off = ((size_t)(b * NH + hh) * SEQ + n) * HD;
    *(unsigned*)&Qhi[off + j]      = pack_hi2(qr0, qr1);
    *(unsigned*)&Qhi[off + j + 32] = pack_hi2(qs0, qs1);
    *(unsigned*)&Qlo[off + j]      = pack_lo2(qr0, qr1);
    *(unsigned*)&Qlo[off + j + 32] = pack_lo2(qs0, qs1);
    *(unsigned*)&Khi[off + j]      = pack_hi2(kr0, kr1);
    *(unsigned*)&Khi[off + j + 32] = pack_hi2(ks0, ks1);
    *(unsigned*)&Klo[off + j]      = pack_lo2(kr0, kr1);
    *(unsigned*)&Klo[off + j + 32] = pack_lo2(ks0, ks1);
}

// ===========================================================================
// Prep: V transpose + split  ([B*H][64][SEQ] hi/lo)
// ===========================================================================
__global__ __launch_bounds__(256) void prep_v_kernel(
    const float* __restrict__ qkv,
    __nv_bfloat16* __restrict__ Vthi, __nv_bfloat16* __restrict__ Vtlo)
{
    __shared__ float ts[64][65];
    const int tid = threadIdx.x;
    const int tile = blockIdx.x;        // bh*32 + ntile
    const int bh = tile >> 5;
    const int k0 = (tile & 31) * 64;
    const int b = bh >> 4, hh = bh & 15;

    for (int i = tid; i < 4096; i += 256) {
        const int r = i >> 6, c = i & 63;
        ts[c][r] = qkv[((size_t)(b * SEQ + k0 + r) * 3 + 2) * DIMC + hh * HD + c];
    }
    __syncthreads();
    for (int i = tid; i < 4096; i += 256) {
        const int d = i >> 6, n = i & 63;
        const float v = ts[d][n];
        const __nv_bfloat16 h = __float2bfloat16(v);
        const size_t off = ((size_t)bh * HD + d) * SEQ + k0 + n;
        Vthi[off] = h;
        Vtlo[off] = __float2bfloat16(v - __bfloat162float(h));
    }
}

// ===========================================================================
// Tensor-core flash attention (non-causal), non-redundant split-bf16.
// Block: 128 q rows x 8 warps; 64-key tiles; 3-stage pipeline (128 KB smem).
// ===========================================================================
#define AQ 128
#define AK 64
#define ANT (SEQ / AK)          // 32 key tiles
#define ASM_QH 0
#define ASM_QL 16384
#define ASM_STG 32768
#define ATILE 8192
#define ASTG_SZ (4 * ATILE)     // 32 KB
#define ASTAGES 3
#define ASM_TOTAL (ASM_STG + ASTAGES * ASTG_SZ)   // 131072

__global__ __launch_bounds__(256, 1) void attn_mma_kernel(
    const __nv_bfloat16* __restrict__ Qhi, const __nv_bfloat16* __restrict__ Qlo,
    const __nv_bfloat16* __restrict__ Khi, const __nv_bfloat16* __restrict__ Klo,
    const __nv_bfloat16* __restrict__ Vthi, const __nv_bfloat16* __restrict__ Vtlo,
    __nv_bfloat16* __restrict__ outhi, __nv_bfloat16* __restrict__ outlo)
{
    extern __shared__ char sm[];
    const unsigned sb = smem_to_u32(sm);
    const int tid = threadIdx.x, wid = tid >> 5, lane = tid & 31;
    const int n0 = blockIdx.x * AQ;
    const int bh = blockIdx.y;
    const int b = bh >> 4, hh = bh & 15;
    const size_t qkrow0 = (size_t)bh * SEQ;

#define A_LOADSTAGE(buf, k0)                                                  \
    do {                                                                      \
        const unsigned s0 = sb + ASM_STG + (unsigned)(buf) * ASTG_SZ;         \
        for (int i = tid; i < 512; i += 256) {                                \
            const int row = i >> 3, ch = i & 7;                               \
            const size_t gk = (qkrow0 + (k0) + row) * HD + ch * 8;            \
            cp_async16(s0 + swz128(row, ch), Khi + gk);                       \
            cp_async16(s0 + ATILE + swz128(row, ch), Klo + gk);               \
            const size_t gv = ((size_t)bh * HD + row) * SEQ + (k0) + ch * 8;  \
            cp_async16(s0 + 2 * ATILE + swz128(row, ch), Vthi + gv);          \
            cp_async16(s0 + 3 * ATILE + swz128(row, ch), Vtlo + gv);          \
        }                                                                     \
    } while (0)

    for (int i = tid; i < 1024; i += 256) {
        const int row = i >> 3, ch = i & 7;
        const size_t gq = (qkrow0 + n0 + row) * HD + ch * 8;
        cp_async16(sb + ASM_QH + swz128(row, ch), Qhi + gq);
        cp_async16(sb + ASM_QL + swz128(row, ch), Qlo + gq);
    }
    A_LOADSTAGE(0, 0);
    cp_commit();
    A_LOADSTAGE(1, AK);
    cp_commit();

    float m0 = -1e30f, m1 = -1e30f, l0 = 0.0f, l1 = 0.0f;
    float o[8][4];
#pragma unroll
    for (int nt = 0; nt < 8; nt++)
#pragma unroll
        for (int c = 0; c < 4; c++) o[nt][c] = 0.0f;

    const int ar = wid * 16 + (lane & 15);           // A ldmatrix row
    const int brq = (lane & 7) + ((lane >> 4) << 3); // B ldmatrix row base
    const int bcq = (lane >> 3) & 1;                 // B chunk phase

    int cur = 0, nxt = 2;
    for (int t = 0; t < ANT; t++) {
        cp_wait<1>();
        __syncthreads();
        if (t + 2 < ANT) { A_LOADSTAGE(nxt, (t + 2) * AK); }
        cp_commit();

        const unsigned s0  = sb + ASM_STG + (unsigned)cur * ASTG_SZ;
        const unsigned s_vh = s0 + 2 * ATILE, s_vl = s0 + 3 * ATILE;

        float p[8][4];
#pragma unroll
        for (int nt = 0; nt < 8; nt++)
#pragma unroll
            for (int c = 0; c < 4; c++) p[nt][c] = 0.0f;

#pragma unroll
        for (int kk = 0; kk < 4; kk++) {
            unsigned ah[4], al[4];
            const unsigned aso = swz128(ar, kk * 2 + (lane >> 4));
            ldm4(ah, sb + ASM_QH + aso);
            ldm4(al, sb + ASM_QL + aso);
            unsigned bhf[4][4], blf[4][4];
#pragma unroll
            for (int ng = 0; ng < 4; ng++) {
                const unsigned bso = swz128(ng * 16 + brq, kk * 2 + bcq);
                ldm4(bhf[ng], s0 + bso);
                ldm4(blf[ng], s0 + ATILE + bso);
            }
#pragma unroll
            for (int nt = 0; nt < 8; nt++)
                mma16816(p[nt], ah, bhf[nt >> 1][(nt & 1) * 2],
                         bhf[nt >> 1][(nt & 1) * 2 + 1]);
#pragma unroll
            for (int nt = 0; nt < 8; nt++)
                mma16816(p[nt], al, bhf[nt >> 1][(nt & 1) * 2],
                         bhf[nt >> 1][(nt & 1) * 2 + 1]);
#pragma unroll
            for (int nt = 0; nt < 8; nt++)
                mma16816(p[nt], ah, blf[nt >> 1][(nt & 1) * 2],
                         blf[nt >> 1][(nt & 1) * 2 + 1]);
        }

        float t0 = -1e30f, t1 = -1e30f;
#pragma unroll
        for (int nt = 0; nt < 8; nt++) {
            t0 = fmaxf(t0, fmaxf(p[nt][0], p[nt][1]));
            t1 = fmaxf(t1, fmaxf(p[nt][2], p[nt][3]));
        }
        t0 = fmaxf(t0, __shfl_xor_sync(0xffffffffu, t0, 1));
        t0 = fmaxf(t0, __shfl_xor_sync(0xffffffffu, t0, 2));
        t1 = fmaxf(t1, __shfl_xor_sync(0xffffffffu, t1, 1));
        t1 = fmaxf(t1, __shfl_xor_sync(0xffffffffu, t1, 2));
        const float mn0 = fmaxf(m0, t0), mn1 = fmaxf(m1, t1);
        const float al0 = __expf(m0 - mn0), al1 = __expf(m1 - mn1);
        m0 = mn0; m1 = mn1;
        float s0s = 0.0f, s1s = 0.0f;
#pragma unroll
        for (int nt = 0; nt < 8; nt++) {
            p[nt][0] = __expf(p[nt][0] - mn0);
            p[nt][1] = __expf(p[nt][1] - mn0);
            p[nt][2] = __expf(p[nt][2] - mn1);
            p[nt][3] = __expf(p[nt][3] - mn1);
            s0s += p[nt][0] + p[nt][1];
            s1s += p[nt][2] + p[nt][3];
        }
        s0s += __shfl_xor_sync(0xffffffffu, s0s, 1);
        s0s += __shfl_xor_sync(0xffffffffu, s0s, 2);
        s1s += __shfl_xor_sync(0xffffffffu, s1s, 1);
        s1s += __shfl_xor_sync(0xffffffffu, s1s, 2);
        l0 = l0 * al0 + s0s;
        l1 = l1 * al1 + s1s;
#pragma unroll
        for (int nt = 0; nt < 8; nt++) {
            o[nt][0] *= al0; o[nt][1] *= al0;
            o[nt][2] *= al1; o[nt][3] *= al1;
        }

#pragma unroll
        for (int kt = 0; kt < 4; kt++) {
            unsigned phi[4], plo[4];
            phi[0] = pack_hi2(p[2 * kt][0], p[2 * kt][1]);
            phi[1] = pack_hi2(p[2 * kt][2], p[2 * kt][3]);
            phi[2] = pack_hi2(p[2 * kt + 1][0], p[2 * kt + 1][1]);
            phi[3] = pack_hi2(p[2 * kt + 1][2], p[2 * kt + 1][3]);
            plo[0] = pack_lo2(p[2 * kt][0], p[2 * kt][1]);
            plo[1] = pack_lo2(p[2 * kt][2], p[2 * kt][3]);
            plo[2] = pack_lo2(p[2 * kt + 1][0], p[2 * kt + 1][1]);
            plo[3] = pack_lo2(p[2 * kt + 1][2], p[2 * kt + 1][3]);
#pragma unroll
            for (int ng = 0; ng < 4; ng++) {
                unsigned bhf[4], blf[4];
                const unsigned bso = swz128(ng * 16 + brq, kt * 2 + bcq);
                ldm4(bhf, s_vh + bso);
                ldm4(blf, s_vl + bso);
                mma16816(o[2 * ng],     phi, bhf[0], bhf[1]);
                mma16816(o[2 * ng + 1], phi, bhf[2], bhf[3]);
                mma16816(o[2 * ng],     plo, bhf[0], bhf[1]);
                mma16816(o[2 * ng + 1], plo, bhf[2], bhf[3]);
                mma16816(o[2 * ng],     phi, blf[0], blf[1]);
                mma16816(o[2 * ng + 1], phi, blf[2], blf[3]);
            }
        }
        cur = (cur + 1 == ASTAGES) ? 0 : cur + 1;
        nxt = (nxt + 1 == ASTAGES) ? 0 : nxt + 1;
    }

    const float il0 = 1.0f / l0, il1 = 1.0f / l1;
    const int g = lane >> 2;
    const int row0 = n0 + wid * 16 + g;
    const int row1 = row0 + 8;
#pragma unroll
    for (int nt = 0; nt < 8; nt++) {
        const int d = nt * 8 + (lane & 3) * 2;
        const float x0 = o[nt][0] * il0, x1 = o[nt][1] * il0;
        const float y0 = o[nt][2] * il1, y1 = o[nt][3] * il1;
        const size_t b0 = (size_t)(b * SEQ + row0) * DIMC + hh * HD + d;
        const size_t b1 = (size_t)(b * SEQ + row1) * DIMC + hh * HD + d;
        *(unsigned*)&outhi[b0] = pack_hi2(x0, x1);
        *(unsigned*)&outlo[b0] = pack_lo2(x0, x1);
        *(unsigned*)&outhi[b1] = pack_hi2(y0, y1);
        *(unsigned*)&outlo[b1] = pack_lo2(y0, y1);
    }
#undef A_LOADSTAGE
}

// ===========================================================================
// SwiGLU elementwise -> hi/lo planes (4 elems/thread)
// ===========================================================================
__global__ void silu_split4_kernel(const float* __restrict__ x1,
                                   const float* __restrict__ x2,
                                   __nv_bfloat16* __restrict__ hi,
                                   __nv_bfloat16* __restrict__ lo, int n)
{
    const int i = (blockIdx.x * blockDim.x + threadIdx.x) * 4;
    if (i < n) {
        const float4 a = *(const float4*)(x1 + i);
        const float4 b = *(const float4*)(x2 + i);
        const float v0 = (a.x / (1.0f + expf(-a.x))) * b.x;
        const float v1 = (a.y / (1.0f + expf(-a.y))) * b.y;
        const float v2 = (a.z / (1.0f + expf(-a.z))) * b.z;
        const float v3 = (a.w / (1.0f + expf(-a.w))) * b.w;
        *(uint2*)(hi + i) = make_uint2(pack_hi2(v0, v1), pack_hi2(v2, v3));
        *(uint2*)(lo + i) = make_uint2(pack_lo2(v0, v1), pack_lo2(v2, v3));
    }
}

// ===========================================================================
// kernel_launch  (my launch index 3 = QKV GEMM = ncu capture position)
// ===========================================================================
extern "C" void kernel_launch(void* const* d_in, const int* in_sizes, int n_in,
                              void* d_out, int out_size)
{
    const float* x      = (const float*)d_in[0];
    const float* qkv_w  = (const float*)d_in[1];
    const float* proj_w = (const float*)d_in[2];
    const float* proj_b = (const float*)d_in[3];
    const float* w1_w   = (const float*)d_in[4];
    const float* w1_b   = (const float*)d_in[5];
    const float* w2_w   = (const float*)d_in[6];
    const float* w2_b   = (const float*)d_in[7];
    const float* w3_w   = (const float*)d_in[8];
    const float* w3_b   = (const float*)d_in[9];
    float* out = (float*)d_out;

    cudaFuncSetAttribute(gemm_mma_kernel,
                         cudaFuncAttributeMaxDynamicSharedMemorySize, GSMEM_SZ);
    cudaFuncSetAttribute(attn_mma_kernel,
                         cudaFuncAttributeMaxDynamicSharedMemorySize, ASM_TOTAL);

    float *qkv, *x1, *x2;
    cudaGetSymbolAddress((void**)&qkv, g_qkv);
    cudaGetSymbolAddress((void**)&x1,  g_x1);
    cudaGetSymbolAddress((void**)&x2,  g_x2);
    __nv_bfloat16 *xhi, *xlo, *ahi, *alo, *phi, *plo, *hhi, *hlo;
    __nv_bfloat16 *wqh, *wql, *wph, *wpl, *w1h, *w1l, *w2h, *w2l, *w3h, *w3l;
    __nv_bfloat16 *qhi, *qlo, *khi, *klo, *vthi, *vtlo;
    cudaGetSymbolAddress((void**)&xhi, g_xhi);  cudaGetSymbolAddress((void**)&xlo, g_xlo);
    cudaGetSymbolAddress((void**)&ahi, g_ahi);  cudaGetSymbolAddress((void**)&alo, g_alo);
    cudaGetSymbolAddress((void**)&phi, g_phi);  cudaGetSymbolAddress((void**)&plo, g_plo);
    cudaGetSymbolAddress((void**)&hhi, g_hhi);  cudaGetSymbolAddress((void**)&hlo, g_hlo);
    cudaGetSymbolAddress((void**)&wqh, g_wqkvhi);  cudaGetSymbolAddress((void**)&wql, g_wqkvlo);
    cudaGetSymbolAddress((void**)&wph, g_wprojhi); cudaGetSymbolAddress((void**)&wpl, g_wprojlo);
    cudaGetSymbolAddress((void**)&w1h, g_w1hi);    cudaGetSymbolAddress((void**)&w1l, g_w1lo);
    cudaGetSymbolAddress((void**)&w2h, g_w2hi);    cudaGetSymbolAddress((void**)&w2l, g_w2lo);
    cudaGetSymbolAddress((void**)&w3h, g_w3hi);    cudaGetSymbolAddress((void**)&w3l, g_w3lo);
    cudaGetSymbolAddress((void**)&qhi, g_qhi);  cudaGetSymbolAddress((void**)&qlo, g_qlo);
    cudaGetSymbolAddress((void**)&khi, g_khi);  cudaGetSymbolAddress((void**)&klo, g_klo);
    cudaGetSymbolAddress((void**)&vthi, g_vthi); cudaGetSymbolAddress((void**)&vtlo, g_vtlo);

    // idx 0-2: splits needed for QKV GEMM (+ proj weights)
    split4_kernel<<<(MTOK * DIMC) / 1024, 256>>>(x, xhi, xlo, MTOK * DIMC);
    split4_kernel<<<(3 * DIMC * DIMC) / 1024, 256>>>(qkv_w, wqh, wql, 3 * DIMC * DIMC);
    split4_kernel<<<(DIMC * DIMC) / 1024, 256>>>(proj_w, wph, wpl, DIMC * DIMC);

    // idx 3: QKV projection -> fp32   (ncu capture position)
    gemm_mma_kernel<<<dim3(3 * DIMC / BN, MTOK / BM), 256, GSMEM_SZ>>>(
        xhi, xlo, wqh, wql, nullptr, qkv, nullptr, nullptr, 3 * DIMC, DIMC);

    // Rope + split prep for attention operands
    prep_qk_kernel<<<(BATCH * SEQ * NH * 16) / 256, 256>>>(qkv, qhi, qlo, khi, klo);
    prep_v_kernel<<<BATCH * NH * (SEQ / 64), 256>>>(qkv, vthi, vtlo);

    // Tensor-core attention -> hi/lo planes
    attn_mma_kernel<<<dim3(SEQ / AQ, BATCH * NH), 256, ASM_TOTAL>>>(
        qhi, qlo, khi, klo, vthi, vtlo, ahi, alo);

    // Output projection (+bias) -> hi/lo planes
    gemm_mma_kernel<<<dim3(DIMC / BN, MTOK / BM), 256, GSMEM_SZ>>>(
        ahi, alo, wph, wpl, proj_b, nullptr, phi, plo, DIMC, DIMC);

    // MLP up projections -> fp32
    split4_kernel<<<(HID * DIMC) / 1024, 256>>>(w1_w, w1h, w1l, HID * DIMC);
    gemm_mma_kernel<<<dim3(HID / BN, MTOK / BM), 256, GSMEM_SZ>>>(
        phi, plo, w1h, w1l, w1_b, x1, nullptr, nullptr, HID, DIMC);
    split4_kernel<<<(HID * DIMC) / 1024, 256>>>(w2_w, w2h, w2l, HID * DIMC);
    gemm_mma_kernel<<<dim3(HID / BN, MTOK / BM), 256, GSMEM_SZ>>>(
        phi, plo, w2h, w2l, w2_b, x2, nullptr, nullptr, HID, DIMC);

    // SwiGLU -> hi/lo planes
    silu_split4_kernel<<<(MTOK * HID) / 1024, 256>>>(x1, x2, hhi, hlo, MTOK * HID);

    // w3 split + down projection -> fp32 out
    split4_kernel<<<(DIMC * HID) / 1024, 256>>>(w3_w, w3h, w3l, DIMC * HID);
    gemm_mma_kernel<<<dim3(DIMC / BN, MTOK / BM), 256, GSMEM_SZ>>>(
        hhi, hlo, w3h, w3l, w3_b, out, nullptr, nullptr, DIMC, HID);
}

// round 15
// speedup vs baseline: 1.0731x; 1.0173x over previous
#include <cuda_runtime.h>
#include <cuda_bf16.h>
#include <math.h>

// Problem constants
#define BATCH 4
#define SEQ   2048
#define DIMC  1024
#define NH    16
#define HD    64
#define HID   2048
#define MTOK  (BATCH * SEQ)   // 8192 tokens

// ===========================================================================
// Scratch (static device globals; allocations forbidden)
// ===========================================================================
__device__ float g_qkv[(size_t)MTOK * 3 * DIMC];   // fp32 qkv (pre-rope)
__device__ float g_x1[(size_t)MTOK * HID];
__device__ float g_x2[(size_t)MTOK * HID];

// Separate hi/lo bf16 planes (non-redundant split scheme)
__device__ __align__(256) __nv_bfloat16 g_xhi[(size_t)MTOK * DIMC];
__device__ __align__(256) __nv_bfloat16 g_xlo[(size_t)MTOK * DIMC];
__device__ __align__(256) __nv_bfloat16 g_ahi[(size_t)MTOK * DIMC];   // attn out
__device__ __align__(256) __nv_bfloat16 g_alo[(size_t)MTOK * DIMC];
__device__ __align__(256) __nv_bfloat16 g_phi[(size_t)MTOK * DIMC];   // proj out
__device__ __align__(256) __nv_bfloat16 g_plo[(size_t)MTOK * DIMC];
__device__ __align__(256) __nv_bfloat16 g_hhi[(size_t)MTOK * HID];    // swiglu out
__device__ __align__(256) __nv_bfloat16 g_hlo[(size_t)MTOK * HID];

__device__ __align__(256) __nv_bfloat16 g_wqkvhi[(size_t)3 * DIMC * DIMC];
__device__ __align__(256) __nv_bfloat16 g_wqkvlo[(size_t)3 * DIMC * DIMC];
__device__ __align__(256) __nv_bfloat16 g_wprojhi[(size_t)DIMC * DIMC];
__device__ __align__(256) __nv_bfloat16 g_wprojlo[(size_t)DIMC * DIMC];
__device__ __align__(256) __nv_bfloat16 g_w1hi[(size_t)HID * DIMC];
__device__ __align__(256) __nv_bfloat16 g_w1lo[(size_t)HID * DIMC];
__device__ __align__(256) __nv_bfloat16 g_w2hi[(size_t)HID * DIMC];
__device__ __align__(256) __nv_bfloat16 g_w2lo[(size_t)HID * DIMC];
__device__ __align__(256) __nv_bfloat16 g_w3hi[(size_t)DIMC * HID];
__device__ __align__(256) __nv_bfloat16 g_w3lo[(size_t)DIMC * HID];

// Attention operands, per (b,h): Q/K [B*H][SEQ][64] hi/lo; Vt [B*H][64][SEQ]
__device__ __align__(256) __nv_bfloat16 g_qhi[(size_t)BATCH * NH * SEQ * HD];
__device__ __align__(256) __nv_bfloat16 g_qlo[(size_t)BATCH * NH * SEQ * HD];
__device__ __align__(256) __nv_bfloat16 g_khi[(size_t)BATCH * NH * SEQ * HD];
__device__ __align__(256) __nv_bfloat16 g_klo[(size_t)BATCH * NH * SEQ * HD];
__device__ __align__(256) __nv_bfloat16 g_vthi[(size_t)BATCH * NH * HD * SEQ];
__device__ __align__(256) __nv_bfloat16 g_vtlo[(size_t)BATCH * NH * HD * SEQ];

// ===========================================================================
// Helpers
// ===========================================================================
__device__ __forceinline__ unsigned smem_to_u32(const void* p) {
    unsigned a;
    asm("{ .reg .u64 t; cvta.to.shared.u64 t, %1; cvt.u32.u64 %0, t; }"
        : "=r"(a) : "l"(p));
    return a;
}
__device__ __forceinline__ void cp_async16(unsigned dst, const void* src) {
    asm volatile("cp.async.cg.shared.global [%0], [%1], 16;" :: "r"(dst), "l"(src));
}
__device__ __forceinline__ void cp_commit() {
    asm volatile("cp.async.commit_group;" ::: "memory");
}
template <int N>
__device__ __forceinline__ void cp_wait() {
    asm volatile("cp.async.wait_group %0;" :: "n"(N) : "memory");
}
__device__ __forceinline__ void ldm4(unsigned* r, unsigned addr) {
    asm volatile("ldmatrix.sync.aligned.m8n8.x4.shared.b16 {%0,%1,%2,%3}, [%4];"
        : "=r"(r[0]), "=r"(r[1]), "=r"(r[2]), "=r"(r[3]) : "r"(addr));
}
__device__ __forceinline__ void mma16816(float* d, const unsigned* a,
                                         unsigned b0, unsigned b1) {
    asm volatile(
        "mma.sync.aligned.m16n8k16.row.col.f32.bf16.bf16.f32 "
        "{%0,%1,%2,%3}, {%4,%5,%6,%7}, {%8,%9}, {%0,%1,%2,%3};"
        : "+f"(d[0]), "+f"(d[1]), "+f"(d[2]), "+f"(d[3])
        : "r"(a[0]), "r"(a[1]), "r"(a[2]), "r"(a[3]), "r"(b0), "r"(b1));
}
__device__ __forceinline__ unsigned pack_bf2(__nv_bfloat16 a, __nv_bfloat16 b) {
    unsigned short ua = *(unsigned short*)&a;
    unsigned short ub = *(unsigned short*)&b;
    return (unsigned)ua | ((unsigned)ub << 16);
}
__device__ __forceinline__ unsigned pack_hi2(float a, float b) {
    return pack_bf2(__float2bfloat16(a), __float2bfloat16(b));
}
__device__ __forceinline__ unsigned pack_lo2(float a, float b) {
    const __nv_bfloat16 ha = __float2bfloat16(a);
    const __nv_bfloat16 hb = __float2bfloat16(b);
    return pack_bf2(__float2bfloat16(a - __bfloat162float(ha)),
                    __float2bfloat16(b - __bfloat162float(hb)));
}
__device__ __forceinline__ unsigned swz128(int row, int c) {   // c: 16B chunk 0..7
    return (unsigned)(row * 128 + (((c ^ (row & 7))) << 4));
}

// ===========================================================================
// Vectorized split: fp32 -> separate bf16 hi + lo planes (4 elems/thread)
// ===========================================================================
__global__ void split4_kernel(const float* __restrict__ in,
                              __nv_bfloat16* __restrict__ hi,
                              __nv_bfloat16* __restrict__ lo, int n)
{
    const int i = (blockIdx.x * blockDim.x + threadIdx.x) * 4;
    if (i < n) {
        const float4 v = *(const float4*)(in + i);
        *(uint2*)(hi + i) = make_uint2(pack_hi2(v.x, v.y), pack_hi2(v.z, v.w));
        *(uint2*)(lo + i) = make_uint2(pack_lo2(v.x, v.y), pack_lo2(v.z, v.w));
    }
}

// ===========================================================================
// Non-redundant split-bf16 tensor-core NT GEMM (R14 winner, unchanged):
//   C = Ah·Bh^T + Al·Bh^T + Ah·Bl^T (+ bias)
// BM=64, BN=128, BKP=64; 2 stages x 48KB = 96KB -> 2 CTAs/SM (bubble cover).
// ===========================================================================
#define BM 64
#define BN 128
#define BKP 64
#define TA_BYTES (BM * BKP * 2)          // 8 KB per A plane
#define TB_BYTES (BN * BKP * 2)          // 16 KB per B plane
#define OFF_AL  TA_BYTES                 // 8192
#define OFF_BH  (2 * TA_BYTES)           // 16384
#define OFF_BL  (2 * TA_BYTES + TB_BYTES) // 32768
#define STG_BYTES (2 * TA_BYTES + 2 * TB_BYTES)  // 48 KB
#define GSMEM_SZ (2 * STG_BYTES)         // 96 KB

__global__ __launch_bounds__(256, 2) void gemm_mma_kernel(
    const __nv_bfloat16* __restrict__ Ahi, const __nv_bfloat16* __restrict__ Alo,
    const __nv_bfloat16* __restrict__ Bhi, const __nv_bfloat16* __restrict__ Blo,
    const float* __restrict__ bias,
    float* __restrict__ outf,
    __nv_bfloat16* __restrict__ outhi, __nv_bfloat16* __restrict__ outlo,
    int N, int K)
{
    extern __shared__ char sm[];
    const unsigned sbase = smem_to_u32(sm);
    const int tid = threadIdx.x;
    const int wid = tid >> 5;
    const int lane = tid & 31;
    const int m0 = blockIdx.y * BM;
    const int n0 = blockIdx.x * BN;
    const int mw = (wid & 1) * 32;
    const int nw = (wid >> 1) * 32;

    float acc[2][4][4];
#pragma unroll
    for (int a = 0; a < 2; a++)
#pragma unroll
        for (int b = 0; b < 4; b++)
#pragma unroll
            for (int c = 0; c < 4; c++) acc[a][b][c] = 0.0f;

#define G_LOADSTAGE(st, k0)                                                    \
    do {                                                                       \
        const unsigned s0 = sbase + (unsigned)(st) * STG_BYTES;                \
        _Pragma("unroll")                                                      \
        for (int i = 0; i < 2; i++) {                                          \
            const int idx = tid + i * 256;                                     \
            const int row = idx >> 3, ch = idx & 7;                            \
            const size_t ga = (size_t)(m0 + row) * K + (k0) + ch * 8;          \
            cp_async16(s0 + swz128(row, ch), Ahi + ga);                        \
            cp_async16(s0 + OFF_AL + swz128(row, ch), Alo + ga);               \
        }                                                                      \
        _Pragma("unroll")                                                      \
        for (int i = 0; i < 4; i++) {                                          \
            const int idx = tid + i * 256;                                     \
            const int row = idx >> 3, ch = idx & 7;                            \
            const size_t gb = (size_t)(n0 + row) * K + (k0) + ch * 8;          \
            cp_async16(s0 + OFF_BH + swz128(row, ch), Bhi + gb);               \
            cp_async16(s0 + OFF_BL + swz128(row, ch), Blo + gb);               \
        }                                                                      \
    } while (0)

    const int NKP = K / BKP;
    G_LOADSTAGE(0, 0);
    cp_commit();
    G_LOADSTAGE(1, BKP);
    cp_commit();

    for (int c = 0; c < NKP; c++) {
        if (c < NKP - 1) cp_wait<1>(); else cp_wait<0>();
        __syncthreads();
        const unsigned s0 = sbase + (unsigned)(c & 1) * STG_BYTES;

#pragma unroll
        for (int kk = 0; kk < 4; kk++) {
            unsigned ah[2][4], al[2][4], bh[2][4], bl[2][4];
#pragma unroll
            for (int mt = 0; mt < 2; mt++) {
                const int r = mw + mt * 16 + (lane & 15);
                const unsigned so = swz128(r, kk * 2 + (lane >> 4));
                ldm4(ah[mt], s0 + so);
                ldm4(al[mt], s0 + OFF_AL + so);
            }
#pragma unroll
            for (int ng = 0; ng < 2; ng++) {
                const int r = nw + ng * 16 + (lane & 7) + ((lane >> 4) << 3);
                const unsigned so = swz128(r, kk * 2 + ((lane >> 3) & 1));
                ldm4(bh[ng], s0 + OFF_BH + so);
                ldm4(bl[ng], s0 + OFF_BL + so);
            }
#pragma unroll
            for (int mt = 0; mt < 2; mt++)
#pragma unroll
                for (int nt = 0; nt < 4; nt++)
                    mma16816(acc[mt][nt], ah[mt],
                             bh[nt >> 1][(nt & 1) * 2], bh[nt >> 1][(nt & 1) * 2 + 1]);
#pragma unroll
            for (int mt = 0; mt < 2; mt++)
#pragma unroll
                for (int nt = 0; nt < 4; nt++)
                    mma16816(acc[mt][nt], al[mt],
                             bh[nt >> 1][(nt & 1) * 2], bh[nt >> 1][(nt & 1) * 2 + 1]);
#pragma unroll
            for (int mt = 0; mt < 2; mt++)
#pragma unroll
                for (int nt = 0; nt < 4; nt++)
                    mma16816(acc[mt][nt], ah[mt],
                             bl[nt >> 1][(nt & 1) * 2], bl[nt >> 1][(nt & 1) * 2 + 1]);
        }
        __syncthreads();
        if (c + 2 < NKP) {
            G_LOADSTAGE((c & 1), (c + 2) * BKP);
            cp_commit();
        }
    }

    // Epilogue
#pragma unroll
    for (int mt = 0; mt < 2; mt++) {
#pragma unroll
        for (int nt = 0; nt < 4; nt++) {
            const int row0 = m0 + mw + mt * 16 + (lane >> 2);
            const int col  = n0 + nw + nt * 8 + (lane & 3) * 2;
            float bv0 = 0.0f, bv1 = 0.0f;
            if (bias != nullptr) { bv0 = bias[col]; bv1 = bias[col + 1]; }
#pragma unroll
            for (int h = 0; h < 2; h++) {
                const int row = row0 + h * 8;
                const float v0 = acc[mt][nt][h * 2 + 0] + bv0;
                const float v1 = acc[mt][nt][h * 2 + 1] + bv1;
                const size_t o = (size_t)row * N + col;
                if (outf != nullptr) {
                    *(float2*)&outf[o] = make_float2(v0, v1);
                }
                if (outhi != nullptr) {
                    *(unsigned*)&outhi[o] = pack_hi2(v0, v1);
                    *(unsigned*)&outlo[o] = pack_lo2(v0, v1);
                }
            }
        }
    }
#undef G_LOADSTAGE
}

// ===========================================================================
// Prep: rope + scale + hi/lo split for Q,K  ([B*H][SEQ][64] planes)
// ===========================================================================
__global__ void prep_qk_kernel(const float* __restrict__ qkv,
                               __nv_bfloat16* __restrict__ Qhi,
                               __nv_bfloat16* __restrict__ Qlo,
                               __nv_bfloat16* __restrict__ Khi,
                               __nv_bfloat16* __restrict__ Klo)
{
    const int idx = blockIdx.x * blockDim.x + threadIdx.x;   // 2^21
    const int jp = idx & 15;
    const int hh = (idx >> 4) & 15;
    const int n = (idx >> 8) & 2047;
    const int b = idx >> 19;
    const int j = jp * 2;

    const float f0 = expf(-(float)j * (9.210340371976184f / 32.0f));
    const float f1 = expf(-(float)(j + 1) * (9.210340371976184f / 32.0f));
    float sn0, cs0, sn1, cs1;
    sincosf((float)n * f0, &sn0, &cs0);
    sincosf((float)n * f1, &sn1, &cs1);

    const size_t base = ((size_t)(b * SEQ + n) * 3) * DIMC + hh * HD;
    const float2 qa = *(const float2*)(qkv + base + j);
    const float2 qb = *(const float2*)(qkv + base + j + 32);
    const float2 ka = *(const float2*)(qkv + base + DIMC + j);
    const float2 kb = *(const float2*)(qkv + base + DIMC + j + 32);

    const float qr0 = (qa.x * cs0 - qb.x * sn0) * 0.125f;
    const float qr1 = (qa.y * cs1 - qb.y * sn1) * 0.125f;
    const float qs0 = (qb.x * cs0 + qa.x * sn0) * 0.125f;
    const float qs1 = (qb.y * cs1 + qa.y * sn1) * 0.125f;
    const float kr0 = ka.x * cs0 - kb.x * sn0;
    const float kr1 = ka.y * cs1 - kb.y * sn1;
    const float ks0 = kb.x * cs0 + ka.x * sn0;
    const float ks1 = kb.y * cs1 + ka.y * sn1;

    const size_t off = ((size_t)(b * NH + hh) * SEQ + n) * HD;
    *(unsigned*)&Qhi[off + j]      = pack_hi2(qr0, qr1);
    *(unsigned*)&Qhi[off + j + 32] = pack_hi2(qs0, qs1);
    *(unsigned*)&Qlo[off + j]      = pack_lo2(qr0, qr1);
    *(unsigned*)&Qlo[off + j + 32] = pack_lo2(qs0, qs1);
    *(unsigned*)&Khi[off + j]      = pack_hi2(kr0, kr1);
    *(unsigned*)&Khi[off + j + 32] = pack_hi2(ks0, ks1);
    *(unsigned*)&Klo[off + j]      = pack_lo2(kr0, kr1);
    *(unsigned*)&Klo[off + j + 32] = pack_lo2(ks0, ks1);
}

// ===========================================================================
// Prep: V transpose + split  ([B*H][64][SEQ] hi/lo)
// ===========================================================================
__global__ __launch_bounds__(256) void prep_v_kernel(
    const float* __restrict__ qkv,
    __nv_bfloat16* __restrict__ Vthi, __nv_bfloat16* __restrict__ Vtlo)
{
    __shared__ float ts[64][65];
    const int tid = threadIdx.x;
    const int tile = blockIdx.x;
    const int bh = tile >> 5;
    const int k0 = (tile & 31) * 64;
    const int b = bh >> 4, hh = bh & 15;

    for (int i = tid; i < 4096; i += 256) {
        const int r = i >> 6, c = i & 63;
        ts[c][r] = qkv[((size_t)(b * SEQ + k0 + r) * 3 + 2) * DIMC + hh * HD + c];
    }
    __syncthreads();
    for (int i = tid; i < 4096; i += 256) {
        const int d = i >> 6, n = i & 63;
        const float v = ts[d][n];
        const __nv_bfloat16 h = __float2bfloat16(v);
        const size_t off = ((size_t)bh * HD + d) * SEQ + k0 + n;
        Vthi[off] = h;
        Vtlo[off] = __float2bfloat16(v - __bfloat162float(h));
    }
}

// ===========================================================================
// Tensor-core flash attention, non-redundant split-bf16.
// 2 stages x 32KB + Q 32KB = 96 KB smem -> 2 CTAs/SM (bubble cover).
// S-pass loads K fragments per-ng to cap register pressure (<=128 regs).
// ===========================================================================
#define AQ 128
#define AK 64
#define ANT (SEQ / AK)          // 32 key tiles
#define ASM_QH 0
#define ASM_QL 16384
#define ASM_STG 32768
#define ATILE 8192
#define ASTG_SZ (4 * ATILE)     // 32 KB
#define ASM_TOTAL (ASM_STG + 2 * ASTG_SZ)   // 98304

__global__ __launch_bounds__(256, 2) void attn_mma_kernel(
    const __nv_bfloat16* __restrict__ Qhi, const __nv_bfloat16* __restrict__ Qlo,
    const __nv_bfloat16* __restrict__ Khi, const __nv_bfloat16* __restrict__ Klo,
    const __nv_bfloat16* __restrict__ Vthi, const __nv_bfloat16* __restrict__ Vtlo,
    __nv_bfloat16* __restrict__ outhi, __nv_bfloat16* __restrict__ outlo)
{
    extern __shared__ char sm[];
    const unsigned sb = smem_to_u32(sm);
    const int tid = threadIdx.x, wid = tid >> 5, lane = tid & 31;
    const int n0 = blockIdx.x * AQ;
    const int bh = blockIdx.y;
    const int b = bh >> 4, hh = bh & 15;
    const size_t qkrow0 = (size_t)bh * SEQ;

#define A_LOADSTAGE(buf, k0)                                                  \
    do {                                                                      \
        const unsigned s0 = sb + ASM_STG + (unsigned)(buf) * ASTG_SZ;         \
        for (int i = tid; i < 512; i += 256) {                                \
            const int row = i >> 3, ch = i & 7;                               \
            const size_t gk = (qkrow0 + (k0) + row) * HD + ch * 8;            \
            cp_async16(s0 + swz128(row, ch), Khi + gk);                       \
            cp_async16(s0 + ATILE + swz128(row, ch), Klo + gk);               \
            const size_t gv = ((size_t)bh * HD + row) * SEQ + (k0) + ch * 8;  \
            cp_async16(s0 + 2 * ATILE + swz128(row, ch), Vthi + gv);          \
            cp_async16(s0 + 3 * ATILE + swz128(row, ch), Vtlo + gv);          \
        }                                                                     \
    } while (0)

    for (int i = tid; i < 1024; i += 256) {
        const int row = i >> 3, ch = i & 7;
        const size_t gq = (qkrow0 + n0 + row) * HD + ch * 8;
        cp_async16(sb + ASM_QH + swz128(row, ch), Qhi + gq);
        cp_async16(sb + ASM_QL + swz128(row, ch), Qlo + gq);
    }
    A_LOADSTAGE(0, 0);
    cp_commit();
    A_LOADSTAGE(1, AK);
    cp_commit();

    float m0 = -1e30f, m1 = -1e30f, l0 = 0.0f, l1 = 0.0f;
    float o[8][4];
#pragma unroll
    for (int nt = 0; nt < 8; nt++)
#pragma unroll
        for (int c = 0; c < 4; c++) o[nt][c] = 0.0f;

    const int ar = wid * 16 + (lane & 15);           // A ldmatrix row
    const int brq = (lane & 7) + ((lane >> 4) << 3); // B ldmatrix row base
    const int bcq = (lane >> 3) & 1;                 // B chunk phase

    for (int t = 0; t < ANT; t++) {
        if (t < ANT - 1) cp_wait<1>(); else cp_wait<0>();
        __syncthreads();
        const unsigned s0  = sb + ASM_STG + (unsigned)(t & 1) * ASTG_SZ;
        const unsigned s_vh = s0 + 2 * ATILE, s_vl = s0 + 3 * ATILE;

        // ---- S: per-ng fragment loads (low reg pressure), 3 passes
        float p[8][4];
#pragma unroll
        for (int nt = 0; nt < 8; nt++)
#pragma unroll
            for (int c = 0; c < 4; c++) p[nt][c] = 0.0f;

#pragma unroll
        for (int kk = 0; kk < 4; kk++) {
            unsigned ah[4], al[4];
            const unsigned aso = swz128(ar, kk * 2 + (lane >> 4));
            ldm4(ah, sb + ASM_QH + aso);
            ldm4(al, sb + ASM_QL + aso);
#pragma unroll
            for (int ng = 0; ng < 4; ng++) {
                unsigned bhf[4], blf[4];
                const unsigned bso = swz128(ng * 16 + brq, kk * 2 + bcq);
                ldm4(bhf, s0 + bso);
                ldm4(blf, s0 + ATILE + bso);
                mma16816(p[2 * ng],     ah, bhf[0], bhf[1]);
                mma16816(p[2 * ng + 1], ah, bhf[2], bhf[3]);
                mma16816(p[2 * ng],     al, bhf[0], bhf[1]);
                mma16816(p[2 * ng + 1], al, bhf[2], bhf[3]);
                mma16816(p[2 * ng],     ah, blf[0], blf[1]);
                mma16816(p[2 * ng + 1], ah, blf[2], blf[3]);
            }
        }

        // ---- online softmax (rows g=lane>>2 and g+8; quad reduction)
        float t0 = -1e30f, t1 = -1e30f;
#pragma unroll
        for (int nt = 0; nt < 8; nt++) {
            t0 = fmaxf(t0, fmaxf(p[nt][0], p[nt][1]));
            t1 = fmaxf(t1, fmaxf(p[nt][2], p[nt][3]));
        }
        t0 = fmaxf(t0, __shfl_xor_sync(0xffffffffu, t0, 1));
        t0 = fmaxf(t0, __shfl_xor_sync(0xffffffffu, t0, 2));
        t1 = fmaxf(t1, __shfl_xor_sync(0xffffffffu, t1, 1));
        t1 = fmaxf(t1, __shfl_xor_sync(0xffffffffu, t1, 2));
        const float mn0 = fmaxf(m0, t0), mn1 = fmaxf(m1, t1);
        const float al0 = __expf(m0 - mn0), al1 = __expf(m1 - mn1);
        m0 = mn0; m1 = mn1;
        float s0s = 0.0f, s1s = 0.0f;
#pragma unroll
        for (int nt = 0; nt < 8; nt++) {
            p[nt][0] = __expf(p[nt][0] - mn0);
            p[nt][1] = __expf(p[nt][1] - mn0);
            p[nt][2] = __expf(p[nt][2] - mn1);
            p[nt][3] = __expf(p[nt][3] - mn1);
            s0s += p[nt][0] + p[nt][1];
            s1s += p[nt][2] + p[nt][3];
        }
        s0s += __shfl_xor_sync(0xffffffffu, s0s, 1);
        s0s += __shfl_xor_sync(0xffffffffu, s0s, 2);
        s1s += __shfl_xor_sync(0xffffffffu, s1s, 1);
        s1s += __shfl_xor_sync(0xffffffffu, s1s, 2);
        l0 = l0 * al0 + s0s;
        l1 = l1 * al1 + s1s;
#pragma unroll
        for (int nt = 0; nt < 8; nt++) {
            o[nt][0] *= al0; o[nt][1] *= al0;
            o[nt][2] *= al1; o[nt][3] *= al1;
        }

        // ---- O += P @ V  (3 split terms)
#pragma unroll
        for (int kt = 0; kt < 4; kt++) {
            unsigned phi[4], plo[4];
            phi[0] = pack_hi2(p[2 * kt][0], p[2 * kt][1]);
            phi[1] = pack_hi2(p[2 * kt][2], p[2 * kt][3]);
            phi[2] = pack_hi2(p[2 * kt + 1][0], p[2 * kt + 1][1]);
            phi[3] = pack_hi2(p[2 * kt + 1][2], p[2 * kt + 1][3]);
            plo[0] = pack_lo2(p[2 * kt][0], p[2 * kt][1]);
            plo[1] = pack_lo2(p[2 * kt][2], p[2 * kt][3]);
            plo[2] = pack_lo2(p[2 * kt + 1][0], p[2 * kt + 1][1]);
            plo[3] = pack_lo2(p[2 * kt + 1][2], p[2 * kt + 1][3]);
#pragma unroll
            for (int ng = 0; ng < 4; ng++) {
                unsigned bhf[4], blf[4];
                const unsigned bso = swz128(ng * 16 + brq, kt * 2 + bcq);
                ldm4(bhf, s_vh + bso);
                ldm4(blf, s_vl + bso);
                mma16816(o[2 * ng],     phi, bhf[0], bhf[1]);
                mma16816(o[2 * ng + 1], phi, bhf[2], bhf[3]);
                mma16816(o[2 * ng],     plo, bhf[0], bhf[1]);
                mma16816(o[2 * ng + 1], plo, bhf[2], bhf[3]);
                mma16816(o[2 * ng],     phi, blf[0], blf[1]);
                mma16816(o[2 * ng + 1], phi, blf[2], blf[3]);
            }
        }

        __syncthreads();   // all reads of stage (t&1) done before refill
        if (t + 2 < ANT) {
            A_LOADSTAGE((t & 1), (t + 2) * AK);
            cp_commit();
        }
    }

    // ---- epilogue: normalize, write hi/lo planes [MTOK][DIMC]
    const float il0 = 1.0f / l0, il1 = 1.0f / l1;
    const int g = lane >> 2;
    const int row0 = n0 + wid * 16 + g;
    const int row1 = row0 + 8;
#pragma unroll
    for (int nt = 0; nt < 8; nt++) {
        const int d = nt * 8 + (lane & 3) * 2;
        const float x0 = o[nt][0] * il0, x1 = o[nt][1] * il0;
        const float y0 = o[nt][2] * il1, y1 = o[nt][3] * il1;
        const size_t b0 = (size_t)(b * SEQ + row0) * DIMC + hh * HD + d;
        const size_t b1 = (size_t)(b * SEQ + row1) * DIMC + hh * HD + d;
        *(unsigned*)&outhi[b0] = pack_hi2(x0, x1);
        *(unsigned*)&outlo[b0] = pack_lo2(x0, x1);
        *(unsigned*)&outhi[b1] = pack_hi2(y0, y1);
        *(unsigned*)&outlo[b1] = pack_lo2(y0, y1);
    }
#undef A_LOADSTAGE
}

// ===========================================================================
// SwiGLU elementwise -> hi/lo planes (4 elems/thread)
// ===========================================================================
__global__ void silu_split4_kernel(const float* __restrict__ x1,
                                   const float* __restrict__ x2,
                                   __nv_bfloat16* __restrict__ hi,
                                   __nv_bfloat16* __restrict__ lo, int n)
{
    const int i = (blockIdx.x * blockDim.x + threadIdx.x) * 4;
    if (i < n) {
        const float4 a = *(const float4*)(x1 + i);
        const float4 b = *(const float4*)(x2 + i);
        const float v0 = (a.x / (1.0f + expf(-a.x))) * b.x;
        const float v1 = (a.y / (1.0f + expf(-a.y))) * b.y;
        const float v2 = (a.z / (1.0f + expf(-a.z))) * b.z;
        const float v3 = (a.w / (1.0f + expf(-a.w))) * b.w;
        *(uint2*)(hi + i) = make_uint2(pack_hi2(v0, v1), pack_hi2(v2, v3));
        *(uint2*)(lo + i) = make_uint2(pack_lo2(v0, v1), pack_lo2(v2, v3));
    }
}

// ===========================================================================
// kernel_launch  (my launch index 3 = QKV GEMM = ncu capture position)
// ===========================================================================
extern "C" void kernel_launch(void* const* d_in, const int* in_sizes, int n_in,
                              void* d_out, int out_size)
{
    const float* x      = (const float*)d_in[0];
    const float* qkv_w  = (const float*)d_in[1];
    const float* proj_w = (const float*)d_in[2];
    const float* proj_b = (const float*)d_in[3];
    const float* w1_w   = (const float*)d_in[4];
    const float* w1_b   = (const float*)d_in[5];
    const float* w2_w   = (const float*)d_in[6];
    const float* w2_b   = (const float*)d_in[7];
    const float* w3_w   = (const float*)d_in[8];
    const float* w3_b   = (const float*)d_in[9];
    float* out = (float*)d_out;

    cudaFuncSetAttribute(gemm_mma_kernel,
                         cudaFuncAttributeMaxDynamicSharedMemorySize, GSMEM_SZ);
    cudaFuncSetAttribute(attn_mma_kernel,
                         cudaFuncAttributeMaxDynamicSharedMemorySize, ASM_TOTAL);

    float *qkv, *x1, *x2;
    cudaGetSymbolAddress((void**)&qkv, g_qkv);
    cudaGetSymbolAddress((void**)&x1,  g_x1);
    cudaGetSymbolAddress((void**)&x2,  g_x2);
    __nv_bfloat16 *xhi, *xlo, *ahi, *alo, *phi, *plo, *hhi, *hlo;
    __nv_bfloat16 *wqh, *wql, *wph, *wpl, *w1h, *w1l, *w2h, *w2l, *w3h, *w3l;
    __nv_bfloat16 *qhi, *qlo, *khi, *klo, *vthi, *vtlo;
    cudaGetSymbolAddress((void**)&xhi, g_xhi);  cudaGetSymbolAddress((void**)&xlo, g_xlo);
    cudaGetSymbolAddress((void**)&ahi, g_ahi);  cudaGetSymbolAddress((void**)&alo, g_alo);
    cudaGetSymbolAddress((void**)&phi, g_phi);  cudaGetSymbolAddress((void**)&plo, g_plo);
    cudaGetSymbolAddress((void**)&hhi, g_hhi);  cudaGetSymbolAddress((void**)&hlo, g_hlo);
    cudaGetSymbolAddress((void**)&wqh, g_wqkvhi);  cudaGetSymbolAddress((void**)&wql, g_wqkvlo);
    cudaGetSymbolAddress((void**)&wph, g_wprojhi); cudaGetSymbolAddress((void**)&wpl, g_wprojlo);
    cudaGetSymbolAddress((void**)&w1h, g_w1hi);    cudaGetSymbolAddress((void**)&w1l, g_w1lo);
    cudaGetSymbolAddress((void**)&w2h, g_w2hi);    cudaGetSymbolAddress((void**)&w2l, g_w2lo);
    cudaGetSymbolAddress((void**)&w3h, g_w3hi);    cudaGetSymbolAddress((void**)&w3l, g_w3lo);
    cudaGetSymbolAddress((void**)&qhi, g_qhi);  cudaGetSymbolAddress((void**)&qlo, g_qlo);
    cudaGetSymbolAddress((void**)&khi, g_khi);  cudaGetSymbolAddress((void**)&klo, g_klo);
    cudaGetSymbolAddress((void**)&vthi, g_vthi); cudaGetSymbolAddress((void**)&vtlo, g_vtlo);

    // idx 0-2: splits needed for QKV GEMM (+ proj weights)
    split4_kernel<<<(MTOK * DIMC) / 1024, 256>>>(x, xhi, xlo, MTOK * DIMC);
    split4_kernel<<<(3 * DIMC * DIMC) / 1024, 256>>>(qkv_w, wqh, wql, 3 * DIMC * DIMC);
    split4_kernel<<<(DIMC * DIMC) / 1024, 256>>>(proj_w, wph, wpl, DIMC * DIMC);

    // idx 3: QKV projection -> fp32   (ncu capture position)
    gemm_mma_kernel<<<dim3(3 * DIMC / BN, MTOK / BM), 256, GSMEM_SZ>>>(
        xhi, xlo, wqh, wql, nullptr, qkv, nullptr, nullptr, 3 * DIMC, DIMC);

    // Rope + split prep for attention operands
    prep_qk_kernel<<<(BATCH * SEQ * NH * 16) / 256, 256>>>(qkv, qhi, qlo, khi, klo);
    prep_v_kernel<<<BATCH * NH * (SEQ / 64), 256>>>(qkv, vthi, vtlo);

    // Tensor-core attention -> hi/lo planes
    attn_mma_kernel<<<dim3(SEQ / AQ, BATCH * NH), 256, ASM_TOTAL>>>(
        qhi, qlo, khi, klo, vthi, vtlo, ahi, alo);

    // Output projection (+bias) -> hi/lo planes
    gemm_mma_kernel<<<dim3(DIMC / BN, MTOK / BM), 256, GSMEM_SZ>>>(
        ahi, alo, wph, wpl, proj_b, nullptr, phi, plo, DIMC, DIMC);

    // MLP up projections -> fp32
    split4_kernel<<<(HID * DIMC) / 1024, 256>>>(w1_w, w1h, w1l, HID * DIMC);
    gemm_mma_kernel<<<dim3(HID / BN, MTOK / BM), 256, GSMEM_SZ>>>(
        phi, plo, w1h, w1l, w1_b, x1, nullptr, nullptr, HID, DIMC);
    split4_kernel<<<(HID * DIMC) / 1024, 256>>>(w2_w, w2h, w2l, HID * DIMC);
    gemm_mma_kernel<<<dim3(HID / BN, MTOK / BM), 256, GSMEM_SZ>>>(
        phi, plo, w2h, w2l, w2_b, x2, nullptr, nullptr, HID, DIMC);

    // SwiGLU -> hi/lo planes
    silu_split4_kernel<<<(MTOK * HID) / 1024, 256>>>(x1, x2, hhi, hlo, MTOK * HID);

    // w3 split + down projection -> fp32 out
    split4_kernel<<<(DIMC * HID) / 1024, 256>>>(w3_w, w3h, w3l, DIMC * HID);
    gemm_mma_kernel<<<dim3(DIMC / BN, MTOK / BM), 256, GSMEM_SZ>>>(
        hhi, hlo, w3h, w3l, w3_b, out, nullptr, nullptr, DIMC, HID);
}

// round 16
// speedup vs baseline: 1.0883x; 1.0141x over previous
#include <cuda_runtime.h>
#include <cuda_bf16.h>
#include <math.h>

// Problem constants
#define BATCH 4
#define SEQ   2048
#define DIMC  1024
#define NH    16
#define HD    64
#define HID   2048
#define MTOK  (BATCH * SEQ)   // 8192 tokens

// ===========================================================================
// Scratch (static device globals; allocations forbidden)
// ===========================================================================
__device__ float g_qkv[(size_t)MTOK * 3 * DIMC];   // fp32 qkv (pre-rope)

// Separate hi/lo bf16 planes (non-redundant split scheme)
__device__ __align__(256) __nv_bfloat16 g_xhi[(size_t)MTOK * DIMC];
__device__ __align__(256) __nv_bfloat16 g_xlo[(size_t)MTOK * DIMC];
__device__ __align__(256) __nv_bfloat16 g_ahi[(size_t)MTOK * DIMC];   // attn out
__device__ __align__(256) __nv_bfloat16 g_alo[(size_t)MTOK * DIMC];
__device__ __align__(256) __nv_bfloat16 g_phi[(size_t)MTOK * DIMC];   // proj out
__device__ __align__(256) __nv_bfloat16 g_plo[(size_t)MTOK * DIMC];
__device__ __align__(256) __nv_bfloat16 g_hhi[(size_t)MTOK * HID];    // swiglu out
__device__ __align__(256) __nv_bfloat16 g_hlo[(size_t)MTOK * HID];

__device__ __align__(256) __nv_bfloat16 g_wqkvhi[(size_t)3 * DIMC * DIMC];
__device__ __align__(256) __nv_bfloat16 g_wqkvlo[(size_t)3 * DIMC * DIMC];
__device__ __align__(256) __nv_bfloat16 g_wprojhi[(size_t)DIMC * DIMC];
__device__ __align__(256) __nv_bfloat16 g_wprojlo[(size_t)DIMC * DIMC];
// Interleaved combined up-weights: row 2i = w1_i, row 2i+1 = w2_i
__device__ __align__(256) __nv_bfloat16 g_wchi[(size_t)2 * HID * DIMC];
__device__ __align__(256) __nv_bfloat16 g_wclo[(size_t)2 * HID * DIMC];
__device__ __align__(256) __nv_bfloat16 g_w3hi[(size_t)DIMC * HID];
__device__ __align__(256) __nv_bfloat16 g_w3lo[(size_t)DIMC * HID];

// Attention operands, per (b,h): Q/K [B*H][SEQ][64] hi/lo; Vt [B*H][64][SEQ]
__device__ __align__(256) __nv_bfloat16 g_qhi[(size_t)BATCH * NH * SEQ * HD];
__device__ __align__(256) __nv_bfloat16 g_qlo[(size_t)BATCH * NH * SEQ * HD];
__device__ __align__(256) __nv_bfloat16 g_khi[(size_t)BATCH * NH * SEQ * HD];
__device__ __align__(256) __nv_bfloat16 g_klo[(size_t)BATCH * NH * SEQ * HD];
__device__ __align__(256) __nv_bfloat16 g_vthi[(size_t)BATCH * NH * HD * SEQ];
__device__ __align__(256) __nv_bfloat16 g_vtlo[(size_t)BATCH * NH * HD * SEQ];

// ===========================================================================
// Helpers
// ===========================================================================
__device__ __forceinline__ unsigned smem_to_u32(const void* p) {
    unsigned a;
    asm("{ .reg .u64 t; cvta.to.shared.u64 t, %1; cvt.u32.u64 %0, t; }"
        : "=r"(a) : "l"(p));
    return a;
}
__device__ __forceinline__ void cp_async16(unsigned dst, const void* src) {
    asm volatile("cp.async.cg.shared.global [%0], [%1], 16;" :: "r"(dst), "l"(src));
}
__device__ __forceinline__ void cp_commit() {
    asm volatile("cp.async.commit_group;" ::: "memory");
}
template <int N>
__device__ __forceinline__ void cp_wait() {
    asm volatile("cp.async.wait_group %0;" :: "n"(N) : "memory");
}
__device__ __forceinline__ void ldm4(unsigned* r, unsigned addr) {
    asm volatile("ldmatrix.sync.aligned.m8n8.x4.shared.b16 {%0,%1,%2,%3}, [%4];"
        : "=r"(r[0]), "=r"(r[1]), "=r"(r[2]), "=r"(r[3]) : "r"(addr));
}
__device__ __forceinline__ void mma16816(float* d, const unsigned* a,
                                         unsigned b0, unsigned b1) {
    asm volatile(
        "mma.sync.aligned.m16n8k16.row.col.f32.bf16.bf16.f32 "
        "{%0,%1,%2,%3}, {%4,%5,%6,%7}, {%8,%9}, {%0,%1,%2,%3};"
        : "+f"(d[0]), "+f"(d[1]), "+f"(d[2]), "+f"(d[3])
        : "r"(a[0]), "r"(a[1]), "r"(a[2]), "r"(a[3]), "r"(b0), "r"(b1));
}
__device__ __forceinline__ unsigned pack_bf2(__nv_bfloat16 a, __nv_bfloat16 b) {
    unsigned short ua = *(unsigned short*)&a;
    unsigned short ub = *(unsigned short*)&b;
    return (unsigned)ua | ((unsigned)ub << 16);
}
__device__ __forceinline__ unsigned pack_hi2(float a, float b) {
    return pack_bf2(__float2bfloat16(a), __float2bfloat16(b));
}
__device__ __forceinline__ unsigned pack_lo2(float a, float b) {
    const __nv_bfloat16 ha = __float2bfloat16(a);
    const __nv_bfloat16 hb = __float2bfloat16(b);
    return pack_bf2(__float2bfloat16(a - __bfloat162float(ha)),
                    __float2bfloat16(b - __bfloat162float(hb)));
}
__device__ __forceinline__ unsigned swz128(int row, int c) {   // c: 16B chunk 0..7
    return (unsigned)(row * 128 + (((c ^ (row & 7))) << 4));
}

// ===========================================================================
// Vectorized split: fp32 -> separate bf16 hi + lo planes (4 elems/thread)
// ===========================================================================
__global__ void split4_kernel(const float* __restrict__ in,
                              __nv_bfloat16* __restrict__ hi,
                              __nv_bfloat16* __restrict__ lo, int n)
{
    const int i = (blockIdx.x * blockDim.x + threadIdx.x) * 4;
    if (i < n) {
        const float4 v = *(const float4*)(in + i);
        *(uint2*)(hi + i) = make_uint2(pack_hi2(v.x, v.y), pack_hi2(v.z, v.w));
        *(uint2*)(lo + i) = make_uint2(pack_lo2(v.x, v.y), pack_lo2(v.z, v.w));
    }
}

// ===========================================================================
// Split + interleave w1/w2 into combined Wc (row 2i = w1_i, row 2i+1 = w2_i)
// ===========================================================================
__global__ void split_interleave_kernel(const float* __restrict__ w1,
                                        const float* __restrict__ w2,
                                        __nv_bfloat16* __restrict__ hi,
                                        __nv_bfloat16* __restrict__ lo)
{
    const int i = (blockIdx.x * blockDim.x + threadIdx.x) * 4;   // over HID*DIMC
    if (i < HID * DIMC) {
        const int r = i / DIMC, k = i - r * DIMC;
        const float4 a = *(const float4*)(w1 + i);
        const float4 b = *(const float4*)(w2 + i);
        const size_t o1 = (size_t)(2 * r) * DIMC + k;
        const size_t o2 = (size_t)(2 * r + 1) * DIMC + k;
        *(uint2*)(hi + o1) = make_uint2(pack_hi2(a.x, a.y), pack_hi2(a.z, a.w));
        *(uint2*)(lo + o1) = make_uint2(pack_lo2(a.x, a.y), pack_lo2(a.z, a.w));
        *(uint2*)(hi + o2) = make_uint2(pack_hi2(b.x, b.y), pack_hi2(b.z, b.w));
        *(uint2*)(lo + o2) = make_uint2(pack_lo2(b.x, b.y), pack_lo2(b.z, b.w));
    }
}

// ===========================================================================
// Non-redundant split-bf16 tensor-core NT GEMM (R14/R15 winner):
//   C = Ah·Bh^T + Al·Bh^T + Ah·Bl^T (+ bias)
// BM=64, BN=128, BKP=64; 2 stages x 48KB = 96KB -> 2 CTAs/SM.
// mode 0: write outf (fp32) and/or outhi/outlo planes.
// mode 1: fused SwiGLU — cols are (x1,x2) pairs; write h=(silu(x1))*x2 to
//         outhi/outlo at [row][col/2] (bias=w1_b, bias2=w2_b).
// ===========================================================================
#define BM 64
#define BN 128
#define BKP 64
#define TA_BYTES (BM * BKP * 2)          // 8 KB per A plane
#define TB_BYTES (BN * BKP * 2)          // 16 KB per B plane
#define OFF_AL  TA_BYTES                 // 8192
#define OFF_BH  (2 * TA_BYTES)           // 16384
#define OFF_BL  (2 * TA_BYTES + TB_BYTES) // 32768
#define STG_BYTES (2 * TA_BYTES + 2 * TB_BYTES)  // 48 KB
#define GSMEM_SZ (2 * STG_BYTES)         // 96 KB

__global__ __launch_bounds__(256, 2) void gemm_mma_kernel(
    const __nv_bfloat16* __restrict__ Ahi, const __nv_bfloat16* __restrict__ Alo,
    const __nv_bfloat16* __restrict__ Bhi, const __nv_bfloat16* __restrict__ Blo,
    const float* __restrict__ bias, const float* __restrict__ bias2,
    float* __restrict__ outf,
    __nv_bfloat16* __restrict__ outhi, __nv_bfloat16* __restrict__ outlo,
    int N, int K, int mode)
{
    extern __shared__ char sm[];
    const unsigned sbase = smem_to_u32(sm);
    const int tid = threadIdx.x;
    const int wid = tid >> 5;
    const int lane = tid & 31;
    const int m0 = blockIdx.y * BM;
    const int n0 = blockIdx.x * BN;
    const int mw = (wid & 1) * 32;
    const int nw = (wid >> 1) * 32;

    float acc[2][4][4];
#pragma unroll
    for (int a = 0; a < 2; a++)
#pragma unroll
        for (int b = 0; b < 4; b++)
#pragma unroll
            for (int c = 0; c < 4; c++) acc[a][b][c] = 0.0f;

#define G_LOADSTAGE(st, k0)                                                    \
    do {                                                                       \
        const unsigned s0 = sbase + (unsigned)(st) * STG_BYTES;                \
        _Pragma("unroll")                                                      \
        for (int i = 0; i < 2; i++) {                                          \
            const int idx = tid + i * 256;                                     \
            const int row = idx >> 3, ch = idx & 7;                            \
            const size_t ga = (size_t)(m0 + row) * K + (k0) + ch * 8;          \
            cp_async16(s0 + swz128(row, ch), Ahi + ga);                        \
            cp_async16(s0 + OFF_AL + swz128(row, ch), Alo + ga);               \
        }                                                                      \
        _Pragma("unroll")                                                      \
        for (int i = 0; i < 4; i++) {                                          \
            const int idx = tid + i * 256;                                     \
            const int row = idx >> 3, ch = idx & 7;                            \
            const size_t gb = (size_t)(n0 + row) * K + (k0) + ch * 8;          \
            cp_async16(s0 + OFF_BH + swz128(row, ch), Bhi + gb);               \
            cp_async16(s0 + OFF_BL + swz128(row, ch), Blo + gb);               \
        }                                                                      \
    } while (0)

    const int NKP = K / BKP;
    G_LOADSTAGE(0, 0);
    cp_commit();
    G_LOADSTAGE(1, BKP);
    cp_commit();

    for (int c = 0; c < NKP; c++) {
        if (c < NKP - 1) cp_wait<1>(); else cp_wait<0>();
        __syncthreads();
        const unsigned s0 = sbase + (unsigned)(c & 1) * STG_BYTES;

#pragma unroll
        for (int kk = 0; kk < 4; kk++) {
            unsigned ah[2][4], al[2][4], bh[2][4], bl[2][4];
#pragma unroll
            for (int mt = 0; mt < 2; mt++) {
                const int r = mw + mt * 16 + (lane & 15);
                const unsigned so = swz128(r, kk * 2 + (lane >> 4));
                ldm4(ah[mt], s0 + so);
                ldm4(al[mt], s0 + OFF_AL + so);
            }
#pragma unroll
            for (int ng = 0; ng < 2; ng++) {
                const int r = nw + ng * 16 + (lane & 7) + ((lane >> 4) << 3);
                const unsigned so = swz128(r, kk * 2 + ((lane >> 3) & 1));
                ldm4(bh[ng], s0 + OFF_BH + so);
                ldm4(bl[ng], s0 + OFF_BL + so);
            }
#pragma unroll
            for (int mt = 0; mt < 2; mt++)
#pragma unroll
                for (int nt = 0; nt < 4; nt++)
                    mma16816(acc[mt][nt], ah[mt],
                             bh[nt >> 1][(nt & 1) * 2], bh[nt >> 1][(nt & 1) * 2 + 1]);
#pragma unroll
            for (int mt = 0; mt < 2; mt++)
#pragma unroll
                for (int nt = 0; nt < 4; nt++)
                    mma16816(acc[mt][nt], al[mt],
                             bh[nt >> 1][(nt & 1) * 2], bh[nt >> 1][(nt & 1) * 2 + 1]);
#pragma unroll
            for (int mt = 0; mt < 2; mt++)
#pragma unroll
                for (int nt = 0; nt < 4; nt++)
                    mma16816(acc[mt][nt], ah[mt],
                             bl[nt >> 1][(nt & 1) * 2], bl[nt >> 1][(nt & 1) * 2 + 1]);
        }
        __syncthreads();
        if (c + 2 < NKP) {
            G_LOADSTAGE((c & 1), (c + 2) * BKP);
            cp_commit();
        }
    }

    // Epilogue
#pragma unroll
    for (int mt = 0; mt < 2; mt++) {
#pragma unroll
        for (int nt = 0; nt < 4; nt++) {
            const int row0 = m0 + mw + mt * 16 + (lane >> 2);
            const int col  = n0 + nw + nt * 8 + (lane & 3) * 2;
#pragma unroll
            for (int h = 0; h < 2; h++) {
                const int row = row0 + h * 8;
                float v0 = acc[mt][nt][h * 2 + 0];
                float v1 = acc[mt][nt][h * 2 + 1];
                if (mode == 0) {
                    if (bias != nullptr) { v0 += bias[col]; v1 += bias[col + 1]; }
                    const size_t o = (size_t)row * N + col;
                    if (outf != nullptr) {
                        *(float2*)&outf[o] = make_float2(v0, v1);
                    }
                    if (outhi != nullptr) {
                        *(unsigned*)&outhi[o] = pack_hi2(v0, v1);
                        *(unsigned*)&outlo[o] = pack_lo2(v0, v1);
                    }
                } else {
                    // fused SwiGLU: (v0,v1) = (x1,x2) for hidden unit col/2
                    const int hid = col >> 1;
                    v0 += bias[hid];
                    v1 += bias2[hid];
                    const float hv = (v0 / (1.0f + expf(-v0))) * v1;
                    const __nv_bfloat16 hb = __float2bfloat16(hv);
                    const size_t o = (size_t)row * (N >> 1) + hid;
                    outhi[o] = hb;
                    outlo[o] = __float2bfloat16(hv - __bfloat162float(hb));
                }
            }
        }
    }
#undef G_LOADSTAGE
}

// ===========================================================================
// Prep: rope + scale + hi/lo split for Q,K  ([B*H][SEQ][64] planes)
// ===========================================================================
__global__ void prep_qk_kernel(const float* __restrict__ qkv,
                               __nv_bfloat16* __restrict__ Qhi,
                               __nv_bfloat16* __restrict__ Qlo,
                               __nv_bfloat16* __restrict__ Khi,
                               __nv_bfloat16* __restrict__ Klo)
{
    const int idx = blockIdx.x * blockDim.x + threadIdx.x;   // 2^21
    const int jp = idx & 15;
    const int hh = (idx >> 4) & 15;
    const int n = (idx >> 8) & 2047;
    const int b = idx >> 19;
    const int j = jp * 2;

    const float f0 = expf(-(float)j * (9.210340371976184f / 32.0f));
    const float f1 = expf(-(float)(j + 1) * (9.210340371976184f / 32.0f));
    float sn0, cs0, sn1, cs1;
    sincosf((float)n * f0, &sn0, &cs0);
    sincosf((float)n * f1, &sn1, &cs1);

    const size_t base = ((size_t)(b * SEQ + n) * 3) * DIMC + hh * HD;
    const float2 qa = *(const float2*)(qkv + base + j);
    const float2 qb = *(const float2*)(qkv + base + j + 32);
    const float2 ka = *(const float2*)(qkv + base + DIMC + j);
    const float2 kb = *(const float2*)(qkv + base + DIMC + j + 32);

    const float qr0 = (qa.x * cs0 - qb.x * sn0) * 0.125f;
    const float qr1 = (qa.y * cs1 - qb.y * sn1) * 0.125f;
    const float qs0 = (qb.x * cs0 + qa.x * sn0) * 0.125f;
    const float qs1 = (qb.y * cs1 + qa.y * sn1) * 0.125f;
    const float kr0 = ka.x * cs0 - kb.x * sn0;
    const float kr1 = ka.y * cs1 - kb.y * sn1;
    const float ks0 = kb.x * cs0 + ka.x * sn0;
    const float ks1 = kb.y * cs1 + ka.y * sn1;

    const size_t off = ((size_t)(b * NH + hh) * SEQ + n) * HD;
    *(unsigned*)&Qhi[off + j]      = pack_hi2(qr0, qr1);
    *(unsigned*)&Qhi[off + j + 32] = pack_hi2(qs0, qs1);
    *(unsigned*)&Qlo[off + j]      = pack_lo2(qr0, qr1);
    *(unsigned*)&Qlo[off + j + 32] = pack_lo2(qs0, qs1);
    *(unsigned*)&Khi[off + j]      = pack_hi2(kr0, kr1);
    *(unsigned*)&Khi[off + j + 32] = pack_hi2(ks0, ks1);
    *(unsigned*)&Klo[off + j]      = pack_lo2(kr0, kr1);
    *(unsigned*)&Klo[off + j + 32] = pack_lo2(ks0, ks1);
}

// ===========================================================================
// Prep: V transpose + split  ([B*H][64][SEQ] hi/lo)
// ===========================================================================
__global__ __launch_bounds__(256) void prep_v_kernel(
    const float* __restrict__ qkv,
    __nv_bfloat16* __restrict__ Vthi, __nv_bfloat16* __restrict__ Vtlo)
{
    __shared__ float ts[64][65];
    const int tid = threadIdx.x;
    const int tile = blockIdx.x;
    const int bh = tile >> 5;
    const int k0 = (tile & 31) * 64;
    const int b = bh >> 4, hh = bh & 15;

    for (int i = tid; i < 4096; i += 256) {
        const int r = i >> 6, c = i & 63;
        ts[c][r] = qkv[((size_t)(b * SEQ + k0 + r) * 3 + 2) * DIMC + hh * HD + c];
    }
    __syncthreads();
    for (int i = tid; i < 4096; i += 256) {
        const int d = i >> 6, n = i & 63;
        const float v = ts[d][n];
        const __nv_bfloat16 h = __float2bfloat16(v);
        const size_t off = ((size_t)bh * HD + d) * SEQ + k0 + n;
        Vthi[off] = h;
        Vtlo[off] = __float2bfloat16(v - __bfloat162float(h));
    }
}

// ===========================================================================
// Tensor-core flash attention (R15 winner, unchanged).
// 2 stages x 32KB + Q 32KB = 96 KB smem -> 2 CTAs/SM.
// ===========================================================================
#define AQ 128
#define AK 64
#define ANT (SEQ / AK)          // 32 key tiles
#define ASM_QH 0
#define ASM_QL 16384
#define ASM_STG 32768
#define ATILE 8192
#define ASTG_SZ (4 * ATILE)     // 32 KB
#define ASM_TOTAL (ASM_STG + 2 * ASTG_SZ)   // 98304

__global__ __launch_bounds__(256, 2) void attn_mma_kernel(
    const __nv_bfloat16* __restrict__ Qhi, const __nv_bfloat16* __restrict__ Qlo,
    const __nv_bfloat16* __restrict__ Khi, const __nv_bfloat16* __restrict__ Klo,
    const __nv_bfloat16* __restrict__ Vthi, const __nv_bfloat16* __restrict__ Vtlo,
    __nv_bfloat16* __restrict__ outhi, __nv_bfloat16* __restrict__ outlo)
{
    extern __shared__ char sm[];
    const unsigned sb = smem_to_u32(sm);
    const int tid = threadIdx.x, wid = tid >> 5, lane = tid & 31;
    const int n0 = blockIdx.x * AQ;
    const int bh = blockIdx.y;
    const int b = bh >> 4, hh = bh & 15;
    const size_t qkrow0 = (size_t)bh * SEQ;

#define A_LOADSTAGE(buf, k0)                                                  \
    do {                                                                      \
        const unsigned s0 = sb + ASM_STG + (unsigned)(buf) * ASTG_SZ;         \
        for (int i = tid; i < 512; i += 256) {                                \
            const int row = i >> 3, ch = i & 7;                               \
            const size_t gk = (qkrow0 + (k0) + row) * HD + ch * 8;            \
            cp_async16(s0 + swz128(row, ch), Khi + gk);                       \
            cp_async16(s0 + ATILE + swz128(row, ch), Klo + gk);               \
            const size_t gv = ((size_t)bh * HD + row) * SEQ + (k0) + ch * 8;  \
            cp_async16(s0 + 2 * ATILE + swz128(row, ch), Vthi + gv);          \
            cp_async16(s0 + 3 * ATILE + swz128(row, ch), Vtlo + gv);          \
        }                                                                     \
    } while (0)

    for (int i = tid; i < 1024; i += 256) {
        const int row = i >> 3, ch = i & 7;
        const size_t gq = (qkrow0 + n0 + row) * HD + ch * 8;
        cp_async16(sb + ASM_QH + swz128(row, ch), Qhi + gq);
        cp_async16(sb + ASM_QL + swz128(row, ch), Qlo + gq);
    }
    A_LOADSTAGE(0, 0);
    cp_commit();
    A_LOADSTAGE(1, AK);
    cp_commit();

    float m0 = -1e30f, m1 = -1e30f, l0 = 0.0f, l1 = 0.0f;
    float o[8][4];
#pragma unroll
    for (int nt = 0; nt < 8; nt++)
#pragma unroll
        for (int c = 0; c < 4; c++) o[nt][c] = 0.0f;

    const int ar = wid * 16 + (lane & 15);
    const int brq = (lane & 7) + ((lane >> 4) << 3);
    const int bcq = (lane >> 3) & 1;

    for (int t = 0; t < ANT; t++) {
        if (t < ANT - 1) cp_wait<1>(); else cp_wait<0>();
        __syncthreads();
        const unsigned s0  = sb + ASM_STG + (unsigned)(t & 1) * ASTG_SZ;
        const unsigned s_vh = s0 + 2 * ATILE, s_vl = s0 + 3 * ATILE;

        float p[8][4];
#pragma unroll
        for (int nt = 0; nt < 8; nt++)
#pragma unroll
            for (int c = 0; c < 4; c++) p[nt][c] = 0.0f;

#pragma unroll
        for (int kk = 0; kk < 4; kk++) {
            unsigned ah[4], al[4];
            const unsigned aso = swz128(ar, kk * 2 + (lane >> 4));
            ldm4(ah, sb + ASM_QH + aso);
            ldm4(al, sb + ASM_QL + aso);
#pragma unroll
            for (int ng = 0; ng < 4; ng++) {
                unsigned bhf[4], blf[4];
                const unsigned bso = swz128(ng * 16 + brq, kk * 2 + bcq);
                ldm4(bhf, s0 + bso);
                ldm4(blf, s0 + ATILE + bso);
                mma16816(p[2 * ng],     ah, bhf[0], bhf[1]);
                mma16816(p[2 * ng + 1], ah, bhf[2], bhf[3]);
                mma16816(p[2 * ng],     al, bhf[0], bhf[1]);
                mma16816(p[2 * ng + 1], al, bhf[2], bhf[3]);
                mma16816(p[2 * ng],     ah, blf[0], blf[1]);
                mma16816(p[2 * ng + 1], ah, blf[2], blf[3]);
            }
        }

        float t0 = -1e30f, t1 = -1e30f;
#pragma unroll
        for (int nt = 0; nt < 8; nt++) {
            t0 = fmaxf(t0, fmaxf(p[nt][0], p[nt][1]));
            t1 = fmaxf(t1, fmaxf(p[nt][2], p[nt][3]));
        }
        t0 = fmaxf(t0, __shfl_xor_sync(0xffffffffu, t0, 1));
        t0 = fmaxf(t0, __shfl_xor_sync(0xffffffffu, t0, 2));
        t1 = fmaxf(t1, __shfl_xor_sync(0xffffffffu, t1, 1));
        t1 = fmaxf(t1, __shfl_xor_sync(0xffffffffu, t1, 2));
        const float mn0 = fmaxf(m0, t0), mn1 = fmaxf(m1, t1);
        const float al0 = __expf(m0 - mn0), al1 = __expf(m1 - mn1);
        m0 = mn0; m1 = mn1;
        float s0s = 0.0f, s1s = 0.0f;
#pragma unroll
        for (int nt = 0; nt < 8; nt++) {
            p[nt][0] = __expf(p[nt][0] - mn0);
            p[nt][1] = __expf(p[nt][1] - mn0);
            p[nt][2] = __expf(p[nt][2] - mn1);
            p[nt][3] = __expf(p[nt][3] - mn1);
            s0s += p[nt][0] + p[nt][1];
            s1s += p[nt][2] + p[nt][3];
        }
        s0s += __shfl_xor_sync(0xffffffffu, s0s, 1);
        s0s += __shfl_xor_sync(0xffffffffu, s0s, 2);
        s1s += __shfl_xor_sync(0xffffffffu, s1s, 1);
        s1s += __shfl_xor_sync(0xffffffffu, s1s, 2);
        l0 = l0 * al0 + s0s;
        l1 = l1 * al1 + s1s;
#pragma unroll
        for (int nt = 0; nt < 8; nt++) {
            o[nt][0] *= al0; o[nt][1] *= al0;
            o[nt][2] *= al1; o[nt][3] *= al1;
        }

#pragma unroll
        for (int kt = 0; kt < 4; kt++) {
            unsigned phi[4], plo[4];
            phi[0] = pack_hi2(p[2 * kt][0], p[2 * kt][1]);
            phi[1] = pack_hi2(p[2 * kt][2], p[2 * kt][3]);
            phi[2] = pack_hi2(p[2 * kt + 1][0], p[2 * kt + 1][1]);
            phi[3] = pack_hi2(p[2 * kt + 1][2], p[2 * kt + 1][3]);
            plo[0] = pack_lo2(p[2 * kt][0], p[2 * kt][1]);
            plo[1] = pack_lo2(p[2 * kt][2], p[2 * kt][3]);
            plo[2] = pack_lo2(p[2 * kt + 1][0], p[2 * kt + 1][1]);
            plo[3] = pack_lo2(p[2 * kt + 1][2], p[2 * kt + 1][3]);
#pragma unroll
            for (int ng = 0; ng < 4; ng++) {
                unsigned bhf[4], blf[4];
                const unsigned bso = swz128(ng * 16 + brq, kt * 2 + bcq);
                ldm4(bhf, s_vh + bso);
                ldm4(blf, s_vl + bso);
                mma16816(o[2 * ng],     phi, bhf[0], bhf[1]);
                mma16816(o[2 * ng + 1], phi, bhf[2], bhf[3]);
                mma16816(o[2 * ng],     plo, bhf[0], bhf[1]);
                mma16816(o[2 * ng + 1], plo, bhf[2], bhf[3]);
                mma16816(o[2 * ng],     phi, blf[0], blf[1]);
                mma16816(o[2 * ng + 1], phi, blf[2], blf[3]);
            }
        }

        __syncthreads();
        if (t + 2 < ANT) {
            A_LOADSTAGE((t & 1), (t + 2) * AK);
            cp_commit();
        }
    }

    const float il0 = 1.0f / l0, il1 = 1.0f / l1;
    const int g = lane >> 2;
    const int row0 = n0 + wid * 16 + g;
    const int row1 = row0 + 8;
#pragma unroll
    for (int nt = 0; nt < 8; nt++) {
        const int d = nt * 8 + (lane & 3) * 2;
        const float x0 = o[nt][0] * il0, x1 = o[nt][1] * il0;
        const float y0 = o[nt][2] * il1, y1 = o[nt][3] * il1;
        const size_t b0 = (size_t)(b * SEQ + row0) * DIMC + hh * HD + d;
        const size_t b1 = (size_t)(b * SEQ + row1) * DIMC + hh * HD + d;
        *(unsigned*)&outhi[b0] = pack_hi2(x0, x1);
        *(unsigned*)&outlo[b0] = pack_lo2(x0, x1);
        *(unsigned*)&outhi[b1] = pack_hi2(y0, y1);
        *(unsigned*)&outlo[b1] = pack_lo2(y0, y1);
    }
#undef A_LOADSTAGE
}

// ===========================================================================
// kernel_launch  (my launch index 3 = QKV GEMM = ncu capture position)
// ===========================================================================
extern "C" void kernel_launch(void* const* d_in, const int* in_sizes, int n_in,
                              void* d_out, int out_size)
{
    const float* x      = (const float*)d_in[0];
    const float* qkv_w  = (const float*)d_in[1];
    const float* proj_w = (const float*)d_in[2];
    const float* proj_b = (const float*)d_in[3];
    const float* w1_w   = (const float*)d_in[4];
    const float* w1_b   = (const float*)d_in[5];
    const float* w2_w   = (const float*)d_in[6];
    const float* w2_b   = (const float*)d_in[7];
    const float* w3_w   = (const float*)d_in[8];
    const float* w3_b   = (const float*)d_in[9];
    float* out = (float*)d_out;

    cudaFuncSetAttribute(gemm_mma_kernel,
                         cudaFuncAttributeMaxDynamicSharedMemorySize, GSMEM_SZ);
    cudaFuncSetAttribute(attn_mma_kernel,
                         cudaFuncAttributeMaxDynamicSharedMemorySize, ASM_TOTAL);

    float *qkv;
    cudaGetSymbolAddress((void**)&qkv, g_qkv);
    __nv_bfloat16 *xhi, *xlo, *ahi, *alo, *phi, *plo, *hhi, *hlo;
    __nv_bfloat16 *wqh, *wql, *wph, *wpl, *wch, *wcl, *w3h, *w3l;
    __nv_bfloat16 *qhi, *qlo, *khi, *klo, *vthi, *vtlo;
    cudaGetSymbolAddress((void**)&xhi, g_xhi);  cudaGetSymbolAddress((void**)&xlo, g_xlo);
    cudaGetSymbolAddress((void**)&ahi, g_ahi);  cudaGetSymbolAddress((void**)&alo, g_alo);
    cudaGetSymbolAddress((void**)&phi, g_phi);  cudaGetSymbolAddress((void**)&plo, g_plo);
    cudaGetSymbolAddress((void**)&hhi, g_hhi);  cudaGetSymbolAddress((void**)&hlo, g_hlo);
    cudaGetSymbolAddress((void**)&wqh, g_wqkvhi);  cudaGetSymbolAddress((void**)&wql, g_wqkvlo);
    cudaGetSymbolAddress((void**)&wph, g_wprojhi); cudaGetSymbolAddress((void**)&wpl, g_wprojlo);
    cudaGetSymbolAddress((void**)&wch, g_wchi);    cudaGetSymbolAddress((void**)&wcl, g_wclo);
    cudaGetSymbolAddress((void**)&w3h, g_w3hi);    cudaGetSymbolAddress((void**)&w3l, g_w3lo);
    cudaGetSymbolAddress((void**)&qhi, g_qhi);  cudaGetSymbolAddress((void**)&qlo, g_qlo);
    cudaGetSymbolAddress((void**)&khi, g_khi);  cudaGetSymbolAddress((void**)&klo, g_klo);
    cudaGetSymbolAddress((void**)&vthi, g_vthi); cudaGetSymbolAddress((void**)&vtlo, g_vtlo);

    // idx 0-2: splits needed for QKV GEMM (+ proj weights)
    split4_kernel<<<(MTOK * DIMC) / 1024, 256>>>(x, xhi, xlo, MTOK * DIMC);
    split4_kernel<<<(3 * DIMC * DIMC) / 1024, 256>>>(qkv_w, wqh, wql, 3 * DIMC * DIMC);
    split4_kernel<<<(DIMC * DIMC) / 1024, 256>>>(proj_w, wph, wpl, DIMC * DIMC);

    // idx 3: QKV projection -> fp32   (ncu capture position)
    gemm_mma_kernel<<<dim3(3 * DIMC / BN, MTOK / BM), 256, GSMEM_SZ>>>(
        xhi, xlo, wqh, wql, nullptr, nullptr, qkv, nullptr, nullptr,
        3 * DIMC, DIMC, 0);

    // Rope + split prep for attention operands
    prep_qk_kernel<<<(BATCH * SEQ * NH * 16) / 256, 256>>>(qkv, qhi, qlo, khi, klo);
    prep_v_kernel<<<BATCH * NH * (SEQ / 64), 256>>>(qkv, vthi, vtlo);

    // Tensor-core attention -> hi/lo planes
    attn_mma_kernel<<<dim3(SEQ / AQ, BATCH * NH), 256, ASM_TOTAL>>>(
        qhi, qlo, khi, klo, vthi, vtlo, ahi, alo);

    // Output projection (+bias) -> hi/lo planes
    gemm_mma_kernel<<<dim3(DIMC / BN, MTOK / BM), 256, GSMEM_SZ>>>(
        ahi, alo, wph, wpl, proj_b, nullptr, nullptr, phi, plo,
        DIMC, DIMC, 0);

    // Combined MLP up (w1 interleaved with w2) + fused SwiGLU -> h hi/lo
    split_interleave_kernel<<<(HID * DIMC) / 1024, 256>>>(w1_w, w2_w, wch, wcl);
    gemm_mma_kernel<<<dim3(2 * HID / BN, MTOK / BM), 256, GSMEM_SZ>>>(
        phi, plo, wch, wcl, w1_b, w2_b, nullptr, hhi, hlo,
        2 * HID, DIMC, 1);

    // w3 split + down projection -> fp32 out
    split4_kernel<<<(DIMC * HID) / 1024, 256>>>(w3_w, w3h, w3l, DIMC * HID);
    gemm_mma_kernel<<<dim3(DIMC / BN, MTOK / BM), 256, GSMEM_SZ>>>(
        hhi, hlo, w3h, w3l, w3_b, nullptr, out, nullptr, nullptr,
        DIMC, HID, 0);
}

// round 17
// speedup vs baseline: 1.0921x; 1.0035x over previous
#include <cuda_runtime.h>
#include <cuda_bf16.h>
#include <math.h>

// Problem constants
#define BATCH 4
#define SEQ   2048
#define DIMC  1024
#define NH    16
#define HD    64
#define HID   2048
#define MTOK  (BATCH * SEQ)   // 8192 tokens

// ===========================================================================
// Scratch (static device globals; allocations forbidden)
// ===========================================================================
__device__ float g_qkv[(size_t)MTOK * 3 * DIMC];   // only V third used now
__device__ __align__(256) float2 g_rope[SEQ * 32]; // (cos,sin) per (n, j)

// Separate hi/lo bf16 planes (non-redundant split scheme)
__device__ __align__(256) __nv_bfloat16 g_xhi[(size_t)MTOK * DIMC];
__device__ __align__(256) __nv_bfloat16 g_xlo[(size_t)MTOK * DIMC];
__device__ __align__(256) __nv_bfloat16 g_ahi[(size_t)MTOK * DIMC];   // attn out
__device__ __align__(256) __nv_bfloat16 g_alo[(size_t)MTOK * DIMC];
__device__ __align__(256) __nv_bfloat16 g_phi[(size_t)MTOK * DIMC];   // proj out
__device__ __align__(256) __nv_bfloat16 g_plo[(size_t)MTOK * DIMC];
__device__ __align__(256) __nv_bfloat16 g_hhi[(size_t)MTOK * HID];    // swiglu out
__device__ __align__(256) __nv_bfloat16 g_hlo[(size_t)MTOK * HID];

__device__ __align__(256) __nv_bfloat16 g_wqkvhi[(size_t)3 * DIMC * DIMC];
__device__ __align__(256) __nv_bfloat16 g_wqkvlo[(size_t)3 * DIMC * DIMC];
__device__ __align__(256) __nv_bfloat16 g_wprojhi[(size_t)DIMC * DIMC];
__device__ __align__(256) __nv_bfloat16 g_wprojlo[(size_t)DIMC * DIMC];
// Interleaved combined up-weights: row 2i = w1_i, row 2i+1 = w2_i
__device__ __align__(256) __nv_bfloat16 g_wchi[(size_t)2 * HID * DIMC];
__device__ __align__(256) __nv_bfloat16 g_wclo[(size_t)2 * HID * DIMC];
__device__ __align__(256) __nv_bfloat16 g_w3hi[(size_t)DIMC * HID];
__device__ __align__(256) __nv_bfloat16 g_w3lo[(size_t)DIMC * HID];

// Attention operands, per (b,h): Q/K [B*H][SEQ][64] hi/lo; Vt [B*H][64][SEQ]
__device__ __align__(256) __nv_bfloat16 g_qhi[(size_t)BATCH * NH * SEQ * HD];
__device__ __align__(256) __nv_bfloat16 g_qlo[(size_t)BATCH * NH * SEQ * HD];
__device__ __align__(256) __nv_bfloat16 g_khi[(size_t)BATCH * NH * SEQ * HD];
__device__ __align__(256) __nv_bfloat16 g_klo[(size_t)BATCH * NH * SEQ * HD];
__device__ __align__(256) __nv_bfloat16 g_vthi[(size_t)BATCH * NH * HD * SEQ];
__device__ __align__(256) __nv_bfloat16 g_vtlo[(size_t)BATCH * NH * HD * SEQ];

// ===========================================================================
// Helpers
// ===========================================================================
__device__ __forceinline__ unsigned smem_to_u32(const void* p) {
    unsigned a;
    asm("{ .reg .u64 t; cvta.to.shared.u64 t, %1; cvt.u32.u64 %0, t; }"
        : "=r"(a) : "l"(p));
    return a;
}
__device__ __forceinline__ void cp_async16(unsigned dst, const void* src) {
    asm volatile("cp.async.cg.shared.global [%0], [%1], 16;" :: "r"(dst), "l"(src));
}
__device__ __forceinline__ void cp_commit() {
    asm volatile("cp.async.commit_group;" ::: "memory");
}
template <int N>
__device__ __forceinline__ void cp_wait() {
    asm volatile("cp.async.wait_group %0;" :: "n"(N) : "memory");
}
__device__ __forceinline__ void ldm4(unsigned* r, unsigned addr) {
    asm volatile("ldmatrix.sync.aligned.m8n8.x4.shared.b16 {%0,%1,%2,%3}, [%4];"
        : "=r"(r[0]), "=r"(r[1]), "=r"(r[2]), "=r"(r[3]) : "r"(addr));
}
__device__ __forceinline__ void mma16816(float* d, const unsigned* a,
                                         unsigned b0, unsigned b1) {
    asm volatile(
        "mma.sync.aligned.m16n8k16.row.col.f32.bf16.bf16.f32 "
        "{%0,%1,%2,%3}, {%4,%5,%6,%7}, {%8,%9}, {%0,%1,%2,%3};"
        : "+f"(d[0]), "+f"(d[1]), "+f"(d[2]), "+f"(d[3])
        : "r"(a[0]), "r"(a[1]), "r"(a[2]), "r"(a[3]), "r"(b0), "r"(b1));
}
__device__ __forceinline__ unsigned pack_bf2(__nv_bfloat16 a, __nv_bfloat16 b) {
    unsigned short ua = *(unsigned short*)&a;
    unsigned short ub = *(unsigned short*)&b;
    return (unsigned)ua | ((unsigned)ub << 16);
}
__device__ __forceinline__ unsigned pack_hi2(float a, float b) {
    return pack_bf2(__float2bfloat16(a), __float2bfloat16(b));
}
__device__ __forceinline__ unsigned pack_lo2(float a, float b) {
    const __nv_bfloat16 ha = __float2bfloat16(a);
    const __nv_bfloat16 hb = __float2bfloat16(b);
    return pack_bf2(__float2bfloat16(a - __bfloat162float(ha)),
                    __float2bfloat16(b - __bfloat162float(hb)));
}
__device__ __forceinline__ unsigned swz128(int row, int c) {   // c: 16B chunk 0..7
    return (unsigned)(row * 128 + (((c ^ (row & 7))) << 4));
}

// ===========================================================================
// Rope table: g_rope[n*32+j] = (cos, sin) of n * 10000^(-j/32)
// ===========================================================================
__global__ void rope_tab_kernel()
{
    const int i = blockIdx.x * blockDim.x + threadIdx.x;   // 65536
    const int j = i & 31, n = i >> 5;
    const float f = expf(-(float)j * (9.210340371976184f / 32.0f));
    float sn, cs;
    sincosf((float)n * f, &sn, &cs);
    g_rope[i] = make_float2(cs, sn);
}

// ===========================================================================
// Vectorized split: fp32 -> separate bf16 hi + lo planes (4 elems/thread)
// ===========================================================================
__global__ void split4_kernel(const float* __restrict__ in,
                              __nv_bfloat16* __restrict__ hi,
                              __nv_bfloat16* __restrict__ lo, int n)
{
    const int i = (blockIdx.x * blockDim.x + threadIdx.x) * 4;
    if (i < n) {
        const float4 v = *(const float4*)(in + i);
        *(uint2*)(hi + i) = make_uint2(pack_hi2(v.x, v.y), pack_hi2(v.z, v.w));
        *(uint2*)(lo + i) = make_uint2(pack_lo2(v.x, v.y), pack_lo2(v.z, v.w));
    }
}

// ===========================================================================
// Split qkv_w with rope-pair row permutation in q/k sections:
// within each head's 64 rows: source j -> dest (2j) if j<32 else (2(j-32)+1).
// v section unpermuted.
// ===========================================================================
__global__ void split_qkvw_kernel(const float* __restrict__ w,
                                  __nv_bfloat16* __restrict__ hi,
                                  __nv_bfloat16* __restrict__ lo)
{
    const int i = (blockIdx.x * blockDim.x + threadIdx.x) * 4;  // 3*DIMC*DIMC
    if (i < 3 * DIMC * DIMC) {
        const int r = i / DIMC, k = i - r * DIMC;
        const int region = r >> 10;
        int rr = r;
        if (region < 2) {
            const int hh = (r & 1023) >> 6, j = r & 63;
            const int p = (j < 32) ? (2 * j) : (2 * (j - 32) + 1);
            rr = (region << 10) + (hh << 6) + p;
        }
        const float4 v = *(const float4*)(w + i);
        const size_t o = (size_t)rr * DIMC + k;
        *(uint2*)(hi + o) = make_uint2(pack_hi2(v.x, v.y), pack_hi2(v.z, v.w));
        *(uint2*)(lo + o) = make_uint2(pack_lo2(v.x, v.y), pack_lo2(v.z, v.w));
    }
}

// ===========================================================================
// Split + interleave w1/w2 into combined Wc (row 2i = w1_i, row 2i+1 = w2_i)
// ===========================================================================
__global__ void split_interleave_kernel(const float* __restrict__ w1,
                                        const float* __restrict__ w2,
                                        __nv_bfloat16* __restrict__ hi,
                                        __nv_bfloat16* __restrict__ lo)
{
    const int i = (blockIdx.x * blockDim.x + threadIdx.x) * 4;   // over HID*DIMC
    if (i < HID * DIMC) {
        const int r = i / DIMC, k = i - r * DIMC;
        const float4 a = *(const float4*)(w1 + i);
        const float4 b = *(const float4*)(w2 + i);
        const size_t o1 = (size_t)(2 * r) * DIMC + k;
        const size_t o2 = (size_t)(2 * r + 1) * DIMC + k;
        *(uint2*)(hi + o1) = make_uint2(pack_hi2(a.x, a.y), pack_hi2(a.z, a.w));
        *(uint2*)(lo + o1) = make_uint2(pack_lo2(a.x, a.y), pack_lo2(a.z, a.w));
        *(uint2*)(hi + o2) = make_uint2(pack_hi2(b.x, b.y), pack_hi2(b.z, b.w));
        *(uint2*)(lo + o2) = make_uint2(pack_lo2(b.x, b.y), pack_lo2(b.z, b.w));
    }
}

// ===========================================================================
// Non-redundant split-bf16 tensor-core NT GEMM (R14/R15 winner):
//   C = Ah·Bh^T + Al·Bh^T + Ah·Bl^T (+ bias)
// BM=64, BN=128, BKP=64; 2 stages x 48KB = 96KB -> 2 CTAs/SM.
// mode 0: standard -> outf fp32 and/or outhi/outlo planes
// mode 1: fused SwiGLU (cols are (x1,x2) pairs) -> h hi/lo
// mode 2: fused QKV: cols<2048 rope pairs -> Q (outhi/outlo) / K (o2hi/o2lo)
//         planes (permuted d-layout); cols>=2048 V fp32 -> outf (g_qkv slice)
// ===========================================================================
#define BM 64
#define BN 128
#define BKP 64
#define TA_BYTES (BM * BKP * 2)          // 8 KB per A plane
#define TB_BYTES (BN * BKP * 2)          // 16 KB per B plane
#define OFF_AL  TA_BYTES                 // 8192
#define OFF_BH  (2 * TA_BYTES)           // 16384
#define OFF_BL  (2 * TA_BYTES + TB_BYTES) // 32768
#define STG_BYTES (2 * TA_BYTES + 2 * TB_BYTES)  // 48 KB
#define GSMEM_SZ (2 * STG_BYTES)         // 96 KB

__global__ __launch_bounds__(256, 2) void gemm_mma_kernel(
    const __nv_bfloat16* __restrict__ Ahi, const __nv_bfloat16* __restrict__ Alo,
    const __nv_bfloat16* __restrict__ Bhi, const __nv_bfloat16* __restrict__ Blo,
    const float* __restrict__ bias, const float* __restrict__ bias2,
    float* __restrict__ outf,
    __nv_bfloat16* __restrict__ outhi, __nv_bfloat16* __restrict__ outlo,
    __nv_bfloat16* __restrict__ o2hi, __nv_bfloat16* __restrict__ o2lo,
    int N, int K, int mode)
{
    extern __shared__ char sm[];
    const unsigned sbase = smem_to_u32(sm);
    const int tid = threadIdx.x;
    const int wid = tid >> 5;
    const int lane = tid & 31;
    const int m0 = blockIdx.y * BM;
    const int n0 = blockIdx.x * BN;
    const int mw = (wid & 1) * 32;
    const int nw = (wid >> 1) * 32;

    float acc[2][4][4];
#pragma unroll
    for (int a = 0; a < 2; a++)
#pragma unroll
        for (int b = 0; b < 4; b++)
#pragma unroll
            for (int c = 0; c < 4; c++) acc[a][b][c] = 0.0f;

#define G_LOADSTAGE(st, k0)                                                    \
    do {                                                                       \
        const unsigned s0 = sbase + (unsigned)(st) * STG_BYTES;                \
        _Pragma("unroll")                                                      \
        for (int i = 0; i < 2; i++) {                                          \
            const int idx = tid + i * 256;                                     \
            const int row = idx >> 3, ch = idx & 7;                            \
            const size_t ga = (size_t)(m0 + row) * K + (k0) + ch * 8;          \
            cp_async16(s0 + swz128(row, ch), Ahi + ga);                        \
            cp_async16(s0 + OFF_AL + swz128(row, ch), Alo + ga);               \
        }                                                                      \
        _Pragma("unroll")                                                      \
        for (int i = 0; i < 4; i++) {                                          \
            const int idx = tid + i * 256;                                     \
            const int row = idx >> 3, ch = idx & 7;                            \
            const size_t gb = (size_t)(n0 + row) * K + (k0) + ch * 8;          \
            cp_async16(s0 + OFF_BH + swz128(row, ch), Bhi + gb);               \
            cp_async16(s0 + OFF_BL + swz128(row, ch), Blo + gb);               \
        }                                                                      \
    } while (0)

    const int NKP = K / BKP;
    G_LOADSTAGE(0, 0);
    cp_commit();
    G_LOADSTAGE(1, BKP);
    cp_commit();

    for (int c = 0; c < NKP; c++) {
        if (c < NKP - 1) cp_wait<1>(); else cp_wait<0>();
        __syncthreads();
        const unsigned s0 = sbase + (unsigned)(c & 1) * STG_BYTES;

#pragma unroll
        for (int kk = 0; kk < 4; kk++) {
            unsigned ah[2][4], al[2][4], bh[2][4], bl[2][4];
#pragma unroll
            for (int mt = 0; mt < 2; mt++) {
                const int r = mw + mt * 16 + (lane & 15);
                const unsigned so = swz128(r, kk * 2 + (lane >> 4));
                ldm4(ah[mt], s0 + so);
                ldm4(al[mt], s0 + OFF_AL + so);
            }
#pragma unroll
            for (int ng = 0; ng < 2; ng++) {
                const int r = nw + ng * 16 + (lane & 7) + ((lane >> 4) << 3);
                const unsigned so = swz128(r, kk * 2 + ((lane >> 3) & 1));
                ldm4(bh[ng], s0 + OFF_BH + so);
                ldm4(bl[ng], s0 + OFF_BL + so);
            }
#pragma unroll
            for (int mt = 0; mt < 2; mt++)
#pragma unroll
                for (int nt = 0; nt < 4; nt++)
                    mma16816(acc[mt][nt], ah[mt],
                             bh[nt >> 1][(nt & 1) * 2], bh[nt >> 1][(nt & 1) * 2 + 1]);
#pragma unroll
            for (int mt = 0; mt < 2; mt++)
#pragma unroll
                for (int nt = 0; nt < 4; nt++)
                    mma16816(acc[mt][nt], al[mt],
                             bh[nt >> 1][(nt & 1) * 2], bh[nt >> 1][(nt & 1) * 2 + 1]);
#pragma unroll
            for (int mt = 0; mt < 2; mt++)
#pragma unroll
                for (int nt = 0; nt < 4; nt++)
                    mma16816(acc[mt][nt], ah[mt],
                             bl[nt >> 1][(nt & 1) * 2], bl[nt >> 1][(nt & 1) * 2 + 1]);
        }
        __syncthreads();
        if (c + 2 < NKP) {
            G_LOADSTAGE((c & 1), (c + 2) * BKP);
            cp_commit();
        }
    }

    // Epilogue
#pragma unroll
    for (int mt = 0; mt < 2; mt++) {
#pragma unroll
        for (int nt = 0; nt < 4; nt++) {
            const int row0 = m0 + mw + mt * 16 + (lane >> 2);
            const int col  = n0 + nw + nt * 8 + (lane & 3) * 2;
#pragma unroll
            for (int h = 0; h < 2; h++) {
                const int row = row0 + h * 8;
                float v0 = acc[mt][nt][h * 2 + 0];
                float v1 = acc[mt][nt][h * 2 + 1];
                if (mode == 0) {
                    if (bias != nullptr) { v0 += bias[col]; v1 += bias[col + 1]; }
                    const size_t o = (size_t)row * N + col;
                    if (outf != nullptr) {
                        *(float2*)&outf[o] = make_float2(v0, v1);
                    }
                    if (outhi != nullptr) {
                        *(unsigned*)&outhi[o] = pack_hi2(v0, v1);
                        *(unsigned*)&outlo[o] = pack_lo2(v0, v1);
                    }
                } else if (mode == 1) {
                    // fused SwiGLU: (v0,v1) = (x1,x2) for hidden unit col/2
                    const int hid = col >> 1;
                    v0 += bias[hid];
                    v1 += bias2[hid];
                    const float hv = (v0 / (1.0f + expf(-v0))) * v1;
                    const __nv_bfloat16 hb = __float2bfloat16(hv);
                    const size_t o = (size_t)row * (N >> 1) + hid;
                    outhi[o] = hb;
                    outlo[o] = __float2bfloat16(hv - __bfloat162float(hb));
                } else {
                    // fused QKV: rope + split for q/k; fp32 for v
                    const int n_tok = row & (SEQ - 1);
                    if (col < 2 * DIMC) {
                        const int reg = col >> 10;
                        const int hh = (col & 1023) >> 6;
                        const int p = col & 63;   // even
                        const float2 cs = g_rope[(n_tok << 5) + (p >> 1)];
                        float r0 = v0 * cs.x - v1 * cs.y;
                        float r1 = v1 * cs.x + v0 * cs.y;
                        const int bidx = row >> 11;
                        const size_t off =
                            ((size_t)(bidx * NH + hh) * SEQ + n_tok) * HD + p;
                        if (reg == 0) {
                            r0 *= 0.125f; r1 *= 0.125f;
                            *(unsigned*)&outhi[off] = pack_hi2(r0, r1);
                            *(unsigned*)&outlo[off] = pack_lo2(r0, r1);
                        } else {
                            *(unsigned*)&o2hi[off] = pack_hi2(r0, r1);
                            *(unsigned*)&o2lo[off] = pack_lo2(r0, r1);
                        }
                    } else {
                        const size_t o =
                            (size_t)row * (3 * DIMC) + 2 * DIMC + (col - 2 * DIMC);
                        *(float2*)&outf[o] = make_float2(v0, v1);
                    }
                }
            }
        }
    }
#undef G_LOADSTAGE
}

// ===========================================================================
// Prep: V transpose + split  ([B*H][64][SEQ] hi/lo)
// ===========================================================================
__global__ __launch_bounds__(256) void prep_v_kernel(
    const float* __restrict__ qkv,
    __nv_bfloat16* __restrict__ Vthi, __nv_bfloat16* __restrict__ Vtlo)
{
    __shared__ float ts[64][65];
    const int tid = threadIdx.x;
    const int tile = blockIdx.x;
    const int bh = tile >> 5;
    const int k0 = (tile & 31) * 64;
    const int b = bh >> 4, hh = bh & 15;

    for (int i = tid; i < 4096; i += 256) {
        const int r = i >> 6, c = i & 63;
        ts[c][r] = qkv[((size_t)(b * SEQ + k0 + r) * 3 + 2) * DIMC + hh * HD + c];
    }
    __syncthreads();
    for (int i = tid; i < 4096; i += 256) {
        const int d = i >> 6, n = i & 63;
        const float v = ts[d][n];
        const __nv_bfloat16 h = __float2bfloat16(v);
        const size_t off = ((size_t)bh * HD + d) * SEQ + k0 + n;
        Vthi[off] = h;
        Vtlo[off] = __float2bfloat16(v - __bfloat162float(h));
    }
}

// ===========================================================================
// Tensor-core flash attention (R15 winner, unchanged).
// 2 stages x 32KB + Q 32KB = 96 KB smem -> 2 CTAs/SM.
// ===========================================================================
#define AQ 128
#define AK 64
#define ANT (SEQ / AK)          // 32 key tiles
#define ASM_QH 0
#define ASM_QL 16384
#define ASM_STG 32768
#define ATILE 8192
#define ASTG_SZ (4 * ATILE)     // 32 KB
#define ASM_TOTAL (ASM_STG + 2 * ASTG_SZ)   // 98304

__global__ __launch_bounds__(256, 2) void attn_mma_kernel(
    const __nv_bfloat16* __restrict__ Qhi, const __nv_bfloat16* __restrict__ Qlo,
    const __nv_bfloat16* __restrict__ Khi, const __nv_bfloat16* __restrict__ Klo,
    const __nv_bfloat16* __restrict__ Vthi, const __nv_bfloat16* __restrict__ Vtlo,
    __nv_bfloat16* __restrict__ outhi, __nv_bfloat16* __restrict__ outlo)
{
    extern __shared__ char sm[];
    const unsigned sb = smem_to_u32(sm);
    const int tid = threadIdx.x, wid = tid >> 5, lane = tid & 31;
    const int n0 = blockIdx.x * AQ;
    const int bh = blockIdx.y;
    const int b = bh >> 4, hh = bh & 15;
    const size_t qkrow0 = (size_t)bh * SEQ;

#define A_LOADSTAGE(buf, k0)                                                  \
    do {                                                                      \
        const unsigned s0 = sb + ASM_STG + (unsigned)(buf) * ASTG_SZ;         \
        for (int i = tid; i < 512; i += 256) {                                \
            const int row = i >> 3, ch = i & 7;                               \
            const size_t gk = (qkrow0 + (k0) + row) * HD + ch * 8;            \
            cp_async16(s0 + swz128(row, ch), Khi + gk);                       \
            cp_async16(s0 + ATILE + swz128(row, ch), Klo + gk);               \
            const size_t gv = ((size_t)bh * HD + row) * SEQ + (k0) + ch * 8;  \
            cp_async16(s0 + 2 * ATILE + swz128(row, ch), Vthi + gv);          \
            cp_async16(s0 + 3 * ATILE + swz128(row, ch), Vtlo + gv);          \
        }                                                                     \
    } while (0)

    for (int i = tid; i < 1024; i += 256) {
        const int row = i >> 3, ch = i & 7;
        const size_t gq = (qkrow0 + n0 + row) * HD + ch * 8;
        cp_async16(sb + ASM_QH + swz128(row, ch), Qhi + gq);
        cp_async16(sb + ASM_QL + swz128(row, ch), Qlo + gq);
    }
    A_LOADSTAGE(0, 0);
    cp_commit();
    A_LOADSTAGE(1, AK);
    cp_commit();

    float m0 = -1e30f, m1 = -1e30f, l0 = 0.0f, l1 = 0.0f;
    float o[8][4];
#pragma unroll
    for (int nt = 0; nt < 8; nt++)
#pragma unroll
        for (int c = 0; c < 4; c++) o[nt][c] = 0.0f;

    const int ar = wid * 16 + (lane & 15);
    const int brq = (lane & 7) + ((lane >> 4) << 3);
    const int bcq = (lane >> 3) & 1;

    for (int t = 0; t < ANT; t++) {
        if (t < ANT - 1) cp_wait<1>(); else cp_wait<0>();
        __syncthreads();
        const unsigned s0  = sb + ASM_STG + (unsigned)(t & 1) * ASTG_SZ;
        const unsigned s_vh = s0 + 2 * ATILE, s_vl = s0 + 3 * ATILE;

        float p[8][4];
#pragma unroll
        for (int nt = 0; nt < 8; nt++)
#pragma unroll
            for (int c = 0; c < 4; c++) p[nt][c] = 0.0f;

#pragma unroll
        for (int kk = 0; kk < 4; kk++) {
            unsigned ah[4], al[4];
            const unsigned aso = swz128(ar, kk * 2 + (lane >> 4));
            ldm4(ah, sb + ASM_QH + aso);
            ldm4(al, sb + ASM_QL + aso);
#pragma unroll
            for (int ng = 0; ng < 4; ng++) {
                unsigned bhf[4], blf[4];
                const unsigned bso = swz128(ng * 16 + brq, kk * 2 + bcq);
                ldm4(bhf, s0 + bso);
                ldm4(blf, s0 + ATILE + bso);
                mma16816(p[2 * ng],     ah, bhf[0], bhf[1]);
                mma16816(p[2 * ng + 1], ah, bhf[2], bhf[3]);
                mma16816(p[2 * ng],     al, bhf[0], bhf[1]);
                mma16816(p[2 * ng + 1], al, bhf[2], bhf[3]);
                mma16816(p[2 * ng],     ah, blf[0], blf[1]);
                mma16816(p[2 * ng + 1], ah, blf[2], blf[3]);
            }
        }

        float t0 = -1e30f, t1 = -1e30f;
#pragma unroll
        for (int nt = 0; nt < 8; nt++) {
            t0 = fmaxf(t0, fmaxf(p[nt][0], p[nt][1]));
            t1 = fmaxf(t1, fmaxf(p[nt][2], p[nt][3]));
        }
        t0 = fmaxf(t0, __shfl_xor_sync(0xffffffffu, t0, 1));
        t0 = fmaxf(t0, __shfl_xor_sync(0xffffffffu, t0, 2));
        t1 = fmaxf(t1, __shfl_xor_sync(0xffffffffu, t1, 1));
        t1 = fmaxf(t1, __shfl_xor_sync(0xffffffffu, t1, 2));
        const float mn0 = fmaxf(m0, t0), mn1 = fmaxf(m1, t1);
        const float al0 = __expf(m0 - mn0), al1 = __expf(m1 - mn1);
        m0 = mn0; m1 = mn1;
        float s0s = 0.0f, s1s = 0.0f;
#pragma unroll
        for (int nt = 0; nt < 8; nt++) {
            p[nt][0] = __expf(p[nt][0] - mn0);
            p[nt][1] = __expf(p[nt][1] - mn0);
            p[nt][2] = __expf(p[nt][2] - mn1);
            p[nt][3] = __expf(p[nt][3] - mn1);
            s0s += p[nt][0] + p[nt][1];
            s1s += p[nt][2] + p[nt][3];
        }
        s0s += __shfl_xor_sync(0xffffffffu, s0s, 1);
        s0s += __shfl_xor_sync(0xffffffffu, s0s, 2);
        s1s += __shfl_xor_sync(0xffffffffu, s1s, 1);
        s1s += __shfl_xor_sync(0xffffffffu, s1s, 2);
        l0 = l0 * al0 + s0s;
        l1 = l1 * al1 + s1s;
#pragma unroll
        for (int nt = 0; nt < 8; nt++) {
            o[nt][0] *= al0; o[nt][1] *= al0;
            o[nt][2] *= al1; o[nt][3] *= al1;
        }

#pragma unroll
        for (int kt = 0; kt < 4; kt++) {
            unsigned phi[4], plo[4];
            phi[0] = pack_hi2(p[2 * kt][0], p[2 * kt][1]);
            phi[1] = pack_hi2(p[2 * kt][2], p[2 * kt][3]);
            phi[2] = pack_hi2(p[2 * kt + 1][0], p[2 * kt + 1][1]);
            phi[3] = pack_hi2(p[2 * kt + 1][2], p[2 * kt + 1][3]);
            plo[0] = pack_lo2(p[2 * kt][0], p[2 * kt][1]);
            plo[1] = pack_lo2(p[2 * kt][2], p[2 * kt][3]);
            plo[2] = pack_lo2(p[2 * kt + 1][0], p[2 * kt + 1][1]);
            plo[3] = pack_lo2(p[2 * kt + 1][2], p[2 * kt + 1][3]);
#pragma unroll
            for (int ng = 0; ng < 4; ng++) {
                unsigned bhf[4], blf[4];
                const unsigned bso = swz128(ng * 16 + brq, kt * 2 + bcq);
                ldm4(bhf, s_vh + bso);
                ldm4(blf, s_vl + bso);
                mma16816(o[2 * ng],     phi, bhf[0], bhf[1]);
                mma16816(o[2 * ng + 1], phi, bhf[2], bhf[3]);
                mma16816(o[2 * ng],     plo, bhf[0], bhf[1]);
                mma16816(o[2 * ng + 1], plo, bhf[2], bhf[3]);
                mma16816(o[2 * ng],     phi, blf[0], blf[1]);
                mma16816(o[2 * ng + 1], phi, blf[2], blf[3]);
            }
        }

        __syncthreads();
        if (t + 2 < ANT) {
            A_LOADSTAGE((t & 1), (t + 2) * AK);
            cp_commit();
        }
    }

    const float il0 = 1.0f / l0, il1 = 1.0f / l1;
    const int g = lane >> 2;
    const int row0 = n0 + wid * 16 + g;
    const int row1 = row0 + 8;
#pragma unroll
    for (int nt = 0; nt < 8; nt++) {
        const int d = nt * 8 + (lane & 3) * 2;
        const float x0 = o[nt][0] * il0, x1 = o[nt][1] * il0;
        const float y0 = o[nt][2] * il1, y1 = o[nt][3] * il1;
        const size_t b0 = (size_t)(b * SEQ + row0) * DIMC + hh * HD + d;
        const size_t b1 = (size_t)(b * SEQ + row1) * DIMC + hh * HD + d;
        *(unsigned*)&outhi[b0] = pack_hi2(x0, x1);
        *(unsigned*)&outlo[b0] = pack_lo2(x0, x1);
        *(unsigned*)&outhi[b1] = pack_hi2(y0, y1);
        *(unsigned*)&outlo[b1] = pack_lo2(y0, y1);
    }
#undef A_LOADSTAGE
}

// ===========================================================================
// kernel_launch  (my launch index 3 = QKV GEMM = ncu capture position)
// ===========================================================================
extern "C" void kernel_launch(void* const* d_in, const int* in_sizes, int n_in,
                              void* d_out, int out_size)
{
    const float* x      = (const float*)d_in[0];
    const float* qkv_w  = (const float*)d_in[1];
    const float* proj_w = (const float*)d_in[2];
    const float* proj_b = (const float*)d_in[3];
    const float* w1_w   = (const float*)d_in[4];
    const float* w1_b   = (const float*)d_in[5];
    const float* w2_w   = (const float*)d_in[6];
    const float* w2_b   = (const float*)d_in[7];
    const float* w3_w   = (const float*)d_in[8];
    const float* w3_b   = (const float*)d_in[9];
    float* out = (float*)d_out;

    cudaFuncSetAttribute(gemm_mma_kernel,
                         cudaFuncAttributeMaxDynamicSharedMemorySize, GSMEM_SZ);
    cudaFuncSetAttribute(attn_mma_kernel,
                         cudaFuncAttributeMaxDynamicSharedMemorySize, ASM_TOTAL);

    float *qkv;
    cudaGetSymbolAddress((void**)&qkv, g_qkv);
    __nv_bfloat16 *xhi, *xlo, *ahi, *alo, *phi, *plo, *hhi, *hlo;
    __nv_bfloat16 *wqh, *wql, *wph, *wpl, *wch, *wcl, *w3h, *w3l;
    __nv_bfloat16 *qhi, *qlo, *khi, *klo, *vthi, *vtlo;
    cudaGetSymbolAddress((void**)&xhi, g_xhi);  cudaGetSymbolAddress((void**)&xlo, g_xlo);
    cudaGetSymbolAddress((void**)&ahi, g_ahi);  cudaGetSymbolAddress((void**)&alo, g_alo);
    cudaGetSymbolAddress((void**)&phi, g_phi);  cudaGetSymbolAddress((void**)&plo, g_plo);
    cudaGetSymbolAddress((void**)&hhi, g_hhi);  cudaGetSymbolAddress((void**)&hlo, g_hlo);
    cudaGetSymbolAddress((void**)&wqh, g_wqkvhi);  cudaGetSymbolAddress((void**)&wql, g_wqkvlo);
    cudaGetSymbolAddress((void**)&wph, g_wprojhi); cudaGetSymbolAddress((void**)&wpl, g_wprojlo);
    cudaGetSymbolAddress((void**)&wch, g_wchi);    cudaGetSymbolAddress((void**)&wcl, g_wclo);
    cudaGetSymbolAddress((void**)&w3h, g_w3hi);    cudaGetSymbolAddress((void**)&w3l, g_w3lo);
    cudaGetSymbolAddress((void**)&qhi, g_qhi);  cudaGetSymbolAddress((void**)&qlo, g_qlo);
    cudaGetSymbolAddress((void**)&khi, g_khi);  cudaGetSymbolAddress((void**)&klo, g_klo);
    cudaGetSymbolAddress((void**)&vthi, g_vthi); cudaGetSymbolAddress((void**)&vtlo, g_vtlo);

    // idx 0-2: x split, permuted qkv_w split, rope table
    split4_kernel<<<(MTOK * DIMC) / 1024, 256>>>(x, xhi, xlo, MTOK * DIMC);
    split_qkvw_kernel<<<(3 * DIMC * DIMC) / 1024, 256>>>(qkv_w, wqh, wql);
    rope_tab_kernel<<<(SEQ * 32) / 256, 256>>>();

    // idx 3: fused QKV projection + rope + split (ncu capture position)
    gemm_mma_kernel<<<dim3(3 * DIMC / BN, MTOK / BM), 256, GSMEM_SZ>>>(
        xhi, xlo, wqh, wql, nullptr, nullptr, qkv, qhi, qlo, khi, klo,
        3 * DIMC, DIMC, 2);

    // V transpose + split
    prep_v_kernel<<<BATCH * NH * (SEQ / 64), 256>>>(qkv, vthi, vtlo);

    // Tensor-core attention -> hi/lo planes
    attn_mma_kernel<<<dim3(SEQ / AQ, BATCH * NH), 256, ASM_TOTAL>>>(
        qhi, qlo, khi, klo, vthi, vtlo, ahi, alo);

    // Output projection (+bias) -> hi/lo planes
    split4_kernel<<<(DIMC * DIMC) / 1024, 256>>>(proj_w, wph, wpl, DIMC * DIMC);
    gemm_mma_kernel<<<dim3(DIMC / BN, MTOK / BM), 256, GSMEM_SZ>>>(
        ahi, alo, wph, wpl, proj_b, nullptr, nullptr, phi, plo, nullptr, nullptr,
        DIMC, DIMC, 0);

    // Combined MLP up (w1 interleaved with w2) + fused SwiGLU -> h hi/lo
    split_interleave_kernel<<<(HID * DIMC) / 1024, 256>>>(w1_w, w2_w, wch, wcl);
    gemm_mma_kernel<<<dim3(2 * HID / BN, MTOK / BM), 256, GSMEM_SZ>>>(
        phi, plo, wch, wcl, w1_b, w2_b, nullptr, hhi, hlo, nullptr, nullptr,
        2 * HID, DIMC, 1);

    // w3 split + down projection -> fp32 out
    split4_kernel<<<(DIMC * HID) / 1024, 256>>>(w3_w, w3h, w3l, DIMC * HID);
    gemm_mma_kernel<<<dim3(DIMC / BN, MTOK / BM), 256, GSMEM_SZ>>>(
        hhi, hlo, w3h, w3l, w3_b, nullptr, out, nullptr, nullptr, nullptr, nullptr,
        DIMC, HID, 0);
}